// round 6
// baseline (speedup 1.0000x reference)
#include <cuda_runtime.h>

#define NN 100000
#define EE 1200000
#define D  64
#define GR 96      // X rows per GEMM block
#define SCH 1024   // scan chunk (elements per scan block)

// Scratch (device globals: no allocation allowed in kernel_launch)
__device__ float g_q[(size_t)NN * D];
__device__ float g_k[(size_t)NN * D];
__device__ float g_v[(size_t)NN * D];
__device__ float g_skip[(size_t)NN * D];
__device__ int   g_counts[NN];
__device__ int   g_offsets[NN];
__device__ int   g_cursor[NN];
__device__ int   g_partial[128];
__device__ int   g_sorted_src[EE];

// ---------------------------------------------------------------------------
// packed f32x2 helpers (Blackwell sm_100+)
// ---------------------------------------------------------------------------
__device__ __forceinline__ unsigned long long dup_f32x2(float x) {
    unsigned long long r;
    asm("mov.b64 %0, {%1, %1};" : "=l"(r) : "f"(x));
    return r;
}
__device__ __forceinline__ void fma_f32x2(unsigned long long& acc,
                                          unsigned long long a,
                                          unsigned long long b) {
    asm("fma.rn.f32x2 %0, %1, %2, %3;" : "=l"(acc) : "l"(a), "l"(b), "l"(acc));
}
__device__ __forceinline__ float2 unpack_f32x2(unsigned long long p) {
    float lo, hi;
    asm("mov.b64 {%0, %1}, %2;" : "=f"(lo), "=f"(hi) : "l"(p));
    return make_float2(lo, hi);
}

// ---------------------------------------------------------------------------
// K1: GEMM. blockIdx.y in {0..3} selects which W/b/Y (q,k,v,skip).
// X tile staged transposed; per thread 4 rows x 8 cols via fma.f32x2.
// smem: xsT 24576B + ws 16384B = 40960B
// ---------------------------------------------------------------------------
__global__ void __launch_bounds__(192) gemm_one(
    const float* __restrict__ X,
    const float* __restrict__ Wq, const float* __restrict__ bq,
    const float* __restrict__ Wk, const float* __restrict__ bk,
    const float* __restrict__ Wv, const float* __restrict__ bv,
    const float* __restrict__ Ws, const float* __restrict__ bs,
    float* __restrict__ Yq, float* __restrict__ Yk,
    float* __restrict__ Yv, float* __restrict__ Ys, int n) {
    __shared__ float xsT[D][GR];   // [k][row]
    __shared__ float ws[D][D];

    int tid  = threadIdx.x;
    int row0 = blockIdx.x * GR;

    const float* W; const float* B; float* Y;
    switch (blockIdx.y) {
        case 0:  W = Wq; B = bq; Y = Yq; break;
        case 1:  W = Wk; B = bk; Y = Yk; break;
        case 2:  W = Wv; B = bv; Y = Yv; break;
        default: W = Ws; B = bs; Y = Ys; break;
    }

    for (int i = tid; i < D * D / 4; i += 192)
        ((float4*)ws)[i] = ((const float4*)W)[i];

    for (int i = tid; i < GR * (D / 4); i += 192) {
        int r  = i % GR;
        int c4 = i / GR;
        float4 v = make_float4(0.f, 0.f, 0.f, 0.f);
        if (row0 + r < n)
            v = ((const float4*)X)[(size_t)(row0 + r) * (D / 4) + c4];
        xsT[c4 * 4 + 0][r] = v.x;
        xsT[c4 * 4 + 1][r] = v.y;
        xsT[c4 * 4 + 2][r] = v.z;
        xsT[c4 * 4 + 3][r] = v.w;
    }
    __syncthreads();

    int tr = (tid >> 3) * 4;  // 0..92
    int tc = (tid & 7) * 8;   // 0..56

    unsigned long long acc[4][4];
#pragma unroll
    for (int r = 0; r < 4; r++)
#pragma unroll
        for (int c = 0; c < 4; c++) acc[r][c] = 0ull;

#pragma unroll 8
    for (int kk = 0; kk < D; kk++) {
        float4 xv = *(const float4*)&xsT[kk][tr];
        ulonglong2 wA = *(const ulonglong2*)&ws[kk][tc];
        ulonglong2 wB = *(const ulonglong2*)&ws[kk][tc + 4];
        unsigned long long x0 = dup_f32x2(xv.x);
        unsigned long long x1 = dup_f32x2(xv.y);
        unsigned long long x2 = dup_f32x2(xv.z);
        unsigned long long x3 = dup_f32x2(xv.w);
        fma_f32x2(acc[0][0], x0, wA.x); fma_f32x2(acc[0][1], x0, wA.y);
        fma_f32x2(acc[0][2], x0, wB.x); fma_f32x2(acc[0][3], x0, wB.y);
        fma_f32x2(acc[1][0], x1, wA.x); fma_f32x2(acc[1][1], x1, wA.y);
        fma_f32x2(acc[1][2], x1, wB.x); fma_f32x2(acc[1][3], x1, wB.y);
        fma_f32x2(acc[2][0], x2, wA.x); fma_f32x2(acc[2][1], x2, wA.y);
        fma_f32x2(acc[2][2], x2, wB.x); fma_f32x2(acc[2][3], x2, wB.y);
        fma_f32x2(acc[3][0], x3, wA.x); fma_f32x2(acc[3][1], x3, wA.y);
        fma_f32x2(acc[3][2], x3, wB.x); fma_f32x2(acc[3][3], x3, wB.y);
    }

    float4 bA = ((const float4*)B)[tc / 4];
    float4 bB = ((const float4*)B)[tc / 4 + 1];
#pragma unroll
    for (int r = 0; r < 4; r++) {
        int grow = row0 + tr + r;
        if (grow < n) {
            float2 p0 = unpack_f32x2(acc[r][0]);
            float2 p1 = unpack_f32x2(acc[r][1]);
            float2 p2 = unpack_f32x2(acc[r][2]);
            float2 p3 = unpack_f32x2(acc[r][3]);
            float4 o0 = make_float4(p0.x + bA.x, p0.y + bA.y,
                                    p1.x + bA.z, p1.y + bA.w);
            float4 o1 = make_float4(p2.x + bB.x, p2.y + bB.y,
                                    p3.x + bB.z, p3.y + bB.w);
            ((float4*)(Y + (size_t)grow * D + tc))[0] = o0;
            ((float4*)(Y + (size_t)grow * D + tc))[1] = o1;
        }
    }
}

// ---------------------------------------------------------------------------
// CSR build: histogram -> 3-phase exclusive scan -> scatter
// ---------------------------------------------------------------------------
__global__ void zero_counts(int n) {
    for (int i = blockIdx.x * blockDim.x + threadIdx.x; i < n;
         i += gridDim.x * blockDim.x)
        g_counts[i] = 0;
}

__global__ void hist_kernel(const int* __restrict__ ei, int E) {
    const int4* d4 = (const int4*)(ei + E);
    int n4 = E >> 2;
    for (int i = blockIdx.x * blockDim.x + threadIdx.x; i < n4;
         i += gridDim.x * blockDim.x) {
        int4 v = d4[i];
        atomicAdd(&g_counts[v.x], 1);
        atomicAdd(&g_counts[v.y], 1);
        atomicAdd(&g_counts[v.z], 1);
        atomicAdd(&g_counts[v.w], 1);
    }
    // tail (E not multiple of 4)
    int t = blockIdx.x * blockDim.x + threadIdx.x;
    if (t < (E & 3)) atomicAdd(&g_counts[ei[E + (n4 << 2) + t]], 1);
}

// per-chunk exclusive scan (256 threads, 4 elems/thread)
__global__ void __launch_bounds__(256) scan1_kernel(int n) {
    __shared__ int sdata[256];
    int t    = threadIdx.x;
    int base = blockIdx.x * SCH + t * 4;

    int v[4];
#pragma unroll
    for (int j = 0; j < 4; j++)
        v[j] = (base + j < n) ? g_counts[base + j] : 0;
    int tsum = v[0] + v[1] + v[2] + v[3];

    sdata[t] = tsum;
    __syncthreads();
    for (int off = 1; off < 256; off <<= 1) {
        int x = (t >= off) ? sdata[t - off] : 0;
        __syncthreads();
        sdata[t] += x;
        __syncthreads();
    }
    int excl = sdata[t] - tsum;
    if (t == 255) g_partial[blockIdx.x] = sdata[255];

    int run = excl;
#pragma unroll
    for (int j = 0; j < 4; j++) {
        if (base + j < n) g_offsets[base + j] = run;
        run += v[j];
    }
}

// parallel exclusive scan over block partials (nblk <= 128)
__global__ void __launch_bounds__(128) scan2_kernel(int nblk) {
    __shared__ int sd[128];
    int t = threadIdx.x;
    int v = (t < nblk) ? g_partial[t] : 0;
    sd[t] = v;
    __syncthreads();
    for (int off = 1; off < 128; off <<= 1) {
        int x = (t >= off) ? sd[t - off] : 0;
        __syncthreads();
        sd[t] += x;
        __syncthreads();
    }
    if (t < nblk) g_partial[t] = sd[t] - v;
}

__global__ void scan3_kernel(int n) {
    for (int i = blockIdx.x * blockDim.x + threadIdx.x; i < n;
         i += gridDim.x * blockDim.x) {
        int o = g_offsets[i] + g_partial[i / SCH];
        g_offsets[i] = o;
        g_cursor[i]  = o;
    }
}

__global__ void scatter_kernel(const int* __restrict__ ei, int E) {
    const int4* s4 = (const int4*)ei;
    const int4* d4 = (const int4*)(ei + E);
    int n4 = E >> 2;
    for (int i = blockIdx.x * blockDim.x + threadIdx.x; i < n4;
         i += gridDim.x * blockDim.x) {
        int4 s = s4[i];
        int4 d = d4[i];
        g_sorted_src[atomicAdd(&g_cursor[d.x], 1)] = s.x;
        g_sorted_src[atomicAdd(&g_cursor[d.y], 1)] = s.y;
        g_sorted_src[atomicAdd(&g_cursor[d.z], 1)] = s.z;
        g_sorted_src[atomicAdd(&g_cursor[d.w], 1)] = s.w;
    }
    int t = blockIdx.x * blockDim.x + threadIdx.x;
    if (t < (E & 3)) {
        int e = (n4 << 2) + t;
        g_sorted_src[atomicAdd(&g_cursor[ei[E + e]], 1)] = ei[e];
    }
}

// ---------------------------------------------------------------------------
// K2: warp-per-destination gather, HALF-WARP per edge.
// Lanes 0-15 take even edges, 16-31 odd edges; each lane holds a float4
// chunk (16 lanes x 16B = full 64-dim row). 4-step xor-shuffle reduces both
// halves simultaneously. Cross-half combine in epilogue.
//   out[dst] = (sum_e exp(q.k_e/8) * v_e) / (sum_e exp + 1e-16) + skip[dst]
// ---------------------------------------------------------------------------
__global__ void __launch_bounds__(256) gather_kernel(
    float* __restrict__ out, int n) {
    int warp = (blockIdx.x * blockDim.x + threadIdx.x) >> 5;
    int lane = threadIdx.x & 31;
    if (warp >= n) return;

    int dst  = warp;
    int beg  = g_offsets[dst];
    int end  = beg + g_counts[dst];
    int half = lane >> 4;   // 0: edges i, 1: edges i+1
    int hl   = lane & 15;   // chunk index within row

    float4 q4 = ((const float4*)(g_q + (size_t)dst * D))[hl];

    float4 acc = make_float4(0.f, 0.f, 0.f, 0.f);
    float  s   = 0.f;

    int i = beg;
    // unroll x2: 4 edges in flight
    for (; i + 3 < end; i += 4) {
        int sA = g_sorted_src[i + half];
        int sB = g_sorted_src[i + 2 + half];
        float4 kA = ((const float4*)(g_k + (size_t)sA * D))[hl];
        float4 kB = ((const float4*)(g_k + (size_t)sB * D))[hl];
        float4 vA = ((const float4*)(g_v + (size_t)sA * D))[hl];
        float4 vB = ((const float4*)(g_v + (size_t)sB * D))[hl];
        float dA = fmaf(q4.x, kA.x, fmaf(q4.y, kA.y, fmaf(q4.z, kA.z, q4.w * kA.w)));
        float dB = fmaf(q4.x, kB.x, fmaf(q4.y, kB.y, fmaf(q4.z, kB.z, q4.w * kB.w)));
#pragma unroll
        for (int o = 8; o > 0; o >>= 1) {
            dA += __shfl_xor_sync(0xffffffffu, dA, o);
            dB += __shfl_xor_sync(0xffffffffu, dB, o);
        }
        float exA = __expf(dA * 0.125f);
        float exB = __expf(dB * 0.125f);
        acc.x = fmaf(exA, vA.x, acc.x); acc.y = fmaf(exA, vA.y, acc.y);
        acc.z = fmaf(exA, vA.z, acc.z); acc.w = fmaf(exA, vA.w, acc.w);
        acc.x = fmaf(exB, vB.x, acc.x); acc.y = fmaf(exB, vB.y, acc.y);
        acc.z = fmaf(exB, vB.z, acc.z); acc.w = fmaf(exB, vB.w, acc.w);
        s += exA + exB;
    }
    for (; i + 1 < end; i += 2) {
        int sA = g_sorted_src[i + half];
        float4 kA = ((const float4*)(g_k + (size_t)sA * D))[hl];
        float4 vA = ((const float4*)(g_v + (size_t)sA * D))[hl];
        float dA = fmaf(q4.x, kA.x, fmaf(q4.y, kA.y, fmaf(q4.z, kA.z, q4.w * kA.w)));
#pragma unroll
        for (int o = 8; o > 0; o >>= 1)
            dA += __shfl_xor_sync(0xffffffffu, dA, o);
        float exA = __expf(dA * 0.125f);
        acc.x = fmaf(exA, vA.x, acc.x); acc.y = fmaf(exA, vA.y, acc.y);
        acc.z = fmaf(exA, vA.z, acc.z); acc.w = fmaf(exA, vA.w, acc.w);
        s += exA;
    }
    if (i < end) {  // odd tail: half 1 contributes zero
        int sA = g_sorted_src[i];
        float4 kA = ((const float4*)(g_k + (size_t)sA * D))[hl];
        float4 vA = ((const float4*)(g_v + (size_t)sA * D))[hl];
        float dA = fmaf(q4.x, kA.x, fmaf(q4.y, kA.y, fmaf(q4.z, kA.z, q4.w * kA.w)));
#pragma unroll
        for (int o = 8; o > 0; o >>= 1)
            dA += __shfl_xor_sync(0xffffffffu, dA, o);
        float exA = half ? 0.f : __expf(dA * 0.125f);
        acc.x = fmaf(exA, vA.x, acc.x); acc.y = fmaf(exA, vA.y, acc.y);
        acc.z = fmaf(exA, vA.z, acc.z); acc.w = fmaf(exA, vA.w, acc.w);
        s += exA;
    }

    // combine halves
    acc.x += __shfl_xor_sync(0xffffffffu, acc.x, 16);
    acc.y += __shfl_xor_sync(0xffffffffu, acc.y, 16);
    acc.z += __shfl_xor_sync(0xffffffffu, acc.z, 16);
    acc.w += __shfl_xor_sync(0xffffffffu, acc.w, 16);
    s     += __shfl_xor_sync(0xffffffffu, s, 16);

    float r = 1.0f / (s + 1e-16f);
    float4 sk = ((const float4*)(g_skip + (size_t)dst * D))[hl];
    float4 o;
    o.x = fmaf(acc.x, r, sk.x);
    o.y = fmaf(acc.y, r, sk.y);
    o.z = fmaf(acc.z, r, sk.z);
    o.w = fmaf(acc.w, r, sk.w);
    if (lane < 16)
        ((float4*)(out + (size_t)dst * D))[hl] = o;
}

// ---------------------------------------------------------------------------
extern "C" void kernel_launch(void* const* d_in, const int* in_sizes, int n_in,
                              void* d_out, int out_size) {
    const float* x  = (const float*)d_in[0];
    const int*   ei = (const int*)d_in[1];   // int64 in ref -> delivered int32
    // d_in[2] = edge_type (unused by reference)
    const float* Wq = (const float*)d_in[3];
    const float* bq = (const float*)d_in[4];
    const float* Wk = (const float*)d_in[5];
    const float* bk = (const float*)d_in[6];
    const float* Wv = (const float*)d_in[7];
    const float* bv = (const float*)d_in[8];
    const float* Ws = (const float*)d_in[9];
    const float* bs = (const float*)d_in[10];
    float* out = (float*)d_out;

    int n = in_sizes[0] / D;   // 100000
    int E = in_sizes[2];       // 1200000
    if (n > NN) n = NN;
    if (E > EE) E = EE;

    float *gq, *gk, *gv, *gsk;
    cudaGetSymbolAddress((void**)&gq,  g_q);
    cudaGetSymbolAddress((void**)&gk,  g_k);
    cudaGetSymbolAddress((void**)&gv,  g_v);
    cudaGetSymbolAddress((void**)&gsk, g_skip);

    int nblk = (n + SCH - 1) / SCH;

    // CSR build
    zero_counts<<<(n + 255) / 256, 256>>>(n);
    hist_kernel<<<(E / 4 + 255) / 256, 256>>>(ei, E);
    scan1_kernel<<<nblk, 256>>>(n);
    scan2_kernel<<<1, 128>>>(nblk);
    scan3_kernel<<<(n + 255) / 256, 256>>>(n);
    scatter_kernel<<<(E / 4 + 255) / 256, 256>>>(ei, E);

    // GEMMs: blockIdx.y selects q/k/v/skip
    {
        dim3 grid((n + GR - 1) / GR, 4);
        gemm_one<<<grid, 192>>>(x, Wq, bq, Wk, bk, Wv, bv, Ws, bs,
                                gq, gk, gv, gsk, n);
    }

    // warp-per-dst gather: attention + normalize + skip, single pass
    {
        int warps_per_block = 8;
        int blocks = (n + warps_per_block - 1) / warps_per_block;
        gather_kernel<<<blocks, 256>>>(out, n);
    }
}

// round 7
// speedup vs baseline: 1.2241x; 1.2241x over previous
#include <cuda_runtime.h>

#define NN 100000
#define EE 1200000
#define D  64
#define GR 128     // X rows per GEMM block
#define SCH 1024   // scan chunk (elements per scan block)

// Scratch (device globals: no allocation allowed in kernel_launch)
__device__ float g_q[(size_t)NN * D];
__device__ float g_k[(size_t)NN * D];
__device__ float g_v[(size_t)NN * D];
__device__ float g_skip[(size_t)NN * D];
__device__ int   g_counts[NN];
__device__ int   g_offsets[NN];   // within-chunk exclusive (scan1 output)
__device__ int   g_cursor[NN];    // global offsets; after scatter = segment END
__device__ int   g_partial[128];
__device__ int   g_sorted_src[EE];

// ---------------------------------------------------------------------------
// packed f32x2 helpers (Blackwell sm_100+)
// ---------------------------------------------------------------------------
__device__ __forceinline__ unsigned long long dup_f32x2(float x) {
    unsigned long long r;
    asm("mov.b64 %0, {%1, %1};" : "=l"(r) : "f"(x));
    return r;
}
__device__ __forceinline__ void fma_f32x2(unsigned long long& acc,
                                          unsigned long long a,
                                          unsigned long long b) {
    asm("fma.rn.f32x2 %0, %1, %2, %3;" : "=l"(acc) : "l"(a), "l"(b), "l"(acc));
}
__device__ __forceinline__ float2 unpack_f32x2(unsigned long long p) {
    float lo, hi;
    asm("mov.b64 {%0, %1}, %2;" : "=f"(lo), "=f"(hi) : "l"(p));
    return make_float2(lo, hi);
}

// ---------------------------------------------------------------------------
// K_GEMM: blockIdx.y in {0..3} selects W/b/Y (q,k,v,skip).
// GR=128 rows x 64 cols per block, 128 threads, 8x8 micro-tile per thread.
// Per k-step: 4 LDS.128 feed 32 fma.f32x2  -> FMA2-bound (fp32x2 floor).
// smem: xsT 32768B + ws 16384B = 49152B (== 48KB static limit)
// ---------------------------------------------------------------------------
__global__ void __launch_bounds__(128) gemm_one(
    const float* __restrict__ X,
    const float* __restrict__ Wq, const float* __restrict__ bq,
    const float* __restrict__ Wk, const float* __restrict__ bk,
    const float* __restrict__ Wv, const float* __restrict__ bv,
    const float* __restrict__ Ws, const float* __restrict__ bs,
    float* __restrict__ Yq, float* __restrict__ Yk,
    float* __restrict__ Yv, float* __restrict__ Ys, int n) {
    __shared__ float xsT[D][GR];   // [k][row]
    __shared__ float ws[D][D];

    int tid  = threadIdx.x;
    int row0 = blockIdx.x * GR;

    const float* W; const float* B; float* Y;
    switch (blockIdx.y) {
        case 0:  W = Wq; B = bq; Y = Yq; break;
        case 1:  W = Wk; B = bk; Y = Yk; break;
        case 2:  W = Wv; B = bv; Y = Yv; break;
        default: W = Ws; B = bs; Y = Ys; break;
    }

    for (int i = tid; i < D * D / 4; i += 128)
        ((float4*)ws)[i] = ((const float4*)W)[i];

    // thread tid stages row (row0+tid), all 16 float4 chunks, transposed
    {
        int r = tid;
        bool ok = (row0 + r < n);
#pragma unroll
        for (int c4 = 0; c4 < D / 4; c4++) {
            float4 v = make_float4(0.f, 0.f, 0.f, 0.f);
            if (ok)
                v = ((const float4*)X)[(size_t)(row0 + r) * (D / 4) + c4];
            xsT[c4 * 4 + 0][r] = v.x;
            xsT[c4 * 4 + 1][r] = v.y;
            xsT[c4 * 4 + 2][r] = v.z;
            xsT[c4 * 4 + 3][r] = v.w;
        }
    }
    __syncthreads();

    int tr = (tid >> 3) * 8;  // 0..120
    int tc = (tid & 7) * 8;   // 0..56

    unsigned long long acc[8][4];
#pragma unroll
    for (int r = 0; r < 8; r++)
#pragma unroll
        for (int c = 0; c < 4; c++) acc[r][c] = 0ull;

#pragma unroll 4
    for (int kk = 0; kk < D; kk++) {
        float4 xa = *(const float4*)&xsT[kk][tr];
        float4 xb = *(const float4*)&xsT[kk][tr + 4];
        ulonglong2 wA = *(const ulonglong2*)&ws[kk][tc];
        ulonglong2 wB = *(const ulonglong2*)&ws[kk][tc + 4];
        unsigned long long xd[8];
        xd[0] = dup_f32x2(xa.x); xd[1] = dup_f32x2(xa.y);
        xd[2] = dup_f32x2(xa.z); xd[3] = dup_f32x2(xa.w);
        xd[4] = dup_f32x2(xb.x); xd[5] = dup_f32x2(xb.y);
        xd[6] = dup_f32x2(xb.z); xd[7] = dup_f32x2(xb.w);
#pragma unroll
        for (int r = 0; r < 8; r++) {
            fma_f32x2(acc[r][0], xd[r], wA.x);
            fma_f32x2(acc[r][1], xd[r], wA.y);
            fma_f32x2(acc[r][2], xd[r], wB.x);
            fma_f32x2(acc[r][3], xd[r], wB.y);
        }
    }

    float4 bA = ((const float4*)B)[tc / 4];
    float4 bB = ((const float4*)B)[tc / 4 + 1];
#pragma unroll
    for (int r = 0; r < 8; r++) {
        int grow = row0 + tr + r;
        if (grow < n) {
            float2 p0 = unpack_f32x2(acc[r][0]);
            float2 p1 = unpack_f32x2(acc[r][1]);
            float2 p2 = unpack_f32x2(acc[r][2]);
            float2 p3 = unpack_f32x2(acc[r][3]);
            float4 o0 = make_float4(p0.x + bA.x, p0.y + bA.y,
                                    p1.x + bA.z, p1.y + bA.w);
            float4 o1 = make_float4(p2.x + bB.x, p2.y + bB.y,
                                    p3.x + bB.z, p3.y + bB.w);
            ((float4*)(Y + (size_t)grow * D + tc))[0] = o0;
            ((float4*)(Y + (size_t)grow * D + tc))[1] = o1;
        }
    }
}

// ---------------------------------------------------------------------------
// CSR build: histogram -> 2-kernel exclusive scan -> scatter
// ---------------------------------------------------------------------------
__global__ void zero_counts(int n) {
    for (int i = blockIdx.x * blockDim.x + threadIdx.x; i < n;
         i += gridDim.x * blockDim.x)
        g_counts[i] = 0;
}

__global__ void hist_kernel(const int* __restrict__ ei, int E) {
    const int4* d4 = (const int4*)(ei + E);
    int n4 = E >> 2;
    for (int i = blockIdx.x * blockDim.x + threadIdx.x; i < n4;
         i += gridDim.x * blockDim.x) {
        int4 v = d4[i];
        atomicAdd(&g_counts[v.x], 1);
        atomicAdd(&g_counts[v.y], 1);
        atomicAdd(&g_counts[v.z], 1);
        atomicAdd(&g_counts[v.w], 1);
    }
    int t = blockIdx.x * blockDim.x + threadIdx.x;
    if (t < (E & 3)) atomicAdd(&g_counts[ei[E + (n4 << 2) + t]], 1);
}

// per-chunk exclusive scan (256 threads, 4 elems/thread)
__global__ void __launch_bounds__(256) scan1_kernel(int n) {
    __shared__ int sdata[256];
    int t    = threadIdx.x;
    int base = blockIdx.x * SCH + t * 4;

    int v[4];
#pragma unroll
    for (int j = 0; j < 4; j++)
        v[j] = (base + j < n) ? g_counts[base + j] : 0;
    int tsum = v[0] + v[1] + v[2] + v[3];

    sdata[t] = tsum;
    __syncthreads();
    for (int off = 1; off < 256; off <<= 1) {
        int x = (t >= off) ? sdata[t - off] : 0;
        __syncthreads();
        sdata[t] += x;
        __syncthreads();
    }
    int excl = sdata[t] - tsum;
    if (t == 255) g_partial[blockIdx.x] = sdata[255];

    int run = excl;
#pragma unroll
    for (int j = 0; j < 4; j++) {
        if (base + j < n) g_offsets[base + j] = run;
        run += v[j];
    }
}

// fused scan2+scan3: every block redundantly scans the (<=128) partials in
// smem, then adds its chunk's base to produce global offsets into g_cursor.
__global__ void __launch_bounds__(256) scan23_kernel(int n, int nblk) {
    __shared__ int sd[128];
    int t = threadIdx.x;
    if (t < 128) {
        int v = (t < nblk) ? g_partial[t] : 0;
        sd[t] = v;
    }
    __syncthreads();
    // Hillis-Steele inclusive scan over 128 slots (first 4 warps cooperate)
    for (int off = 1; off < 128; off <<= 1) {
        int x = 0;
        if (t < 128 && t >= off) x = sd[t - off];
        __syncthreads();
        if (t < 128) sd[t] += x;
        __syncthreads();
    }
    int chunk = blockIdx.x;               // one block per chunk
    int cbase = (chunk > 0) ? sd[chunk - 1] : 0;
    int i0 = chunk * SCH;
    for (int i = i0 + t; i < i0 + SCH && i < n; i += 256)
        g_cursor[i] = g_offsets[i] + cbase;
}

__global__ void scatter_kernel(const int* __restrict__ ei, int E) {
    const int4* s4 = (const int4*)ei;
    const int4* d4 = (const int4*)(ei + E);
    int n4 = E >> 2;
    for (int i = blockIdx.x * blockDim.x + threadIdx.x; i < n4;
         i += gridDim.x * blockDim.x) {
        int4 s = s4[i];
        int4 d = d4[i];
        g_sorted_src[atomicAdd(&g_cursor[d.x], 1)] = s.x;
        g_sorted_src[atomicAdd(&g_cursor[d.y], 1)] = s.y;
        g_sorted_src[atomicAdd(&g_cursor[d.z], 1)] = s.z;
        g_sorted_src[atomicAdd(&g_cursor[d.w], 1)] = s.w;
    }
    int t = blockIdx.x * blockDim.x + threadIdx.x;
    if (t < (E & 3)) {
        int e = (n4 << 2) + t;
        g_sorted_src[atomicAdd(&g_cursor[ei[E + e]], 1)] = ei[e];
    }
}

// ---------------------------------------------------------------------------
// K_GATHER: warp-per-destination, half-warp per edge.
// After scatter, g_cursor[dst] == segment END; beg = end - counts[dst].
// ---------------------------------------------------------------------------
__global__ void __launch_bounds__(256) gather_kernel(
    float* __restrict__ out, int n) {
    int warp = (blockIdx.x * blockDim.x + threadIdx.x) >> 5;
    int lane = threadIdx.x & 31;
    if (warp >= n) return;

    int dst  = warp;
    int end  = g_cursor[dst];
    int beg  = end - g_counts[dst];
    int half = lane >> 4;   // 0: edges i, 1: edges i+1
    int hl   = lane & 15;   // chunk index within row

    float4 q4 = ((const float4*)(g_q + (size_t)dst * D))[hl];

    float4 acc = make_float4(0.f, 0.f, 0.f, 0.f);
    float  s   = 0.f;

    int i = beg;
    for (; i + 3 < end; i += 4) {
        int sA = g_sorted_src[i + half];
        int sB = g_sorted_src[i + 2 + half];
        float4 kA = ((const float4*)(g_k + (size_t)sA * D))[hl];
        float4 kB = ((const float4*)(g_k + (size_t)sB * D))[hl];
        float4 vA = ((const float4*)(g_v + (size_t)sA * D))[hl];
        float4 vB = ((const float4*)(g_v + (size_t)sB * D))[hl];
        float dA = fmaf(q4.x, kA.x, fmaf(q4.y, kA.y, fmaf(q4.z, kA.z, q4.w * kA.w)));
        float dB = fmaf(q4.x, kB.x, fmaf(q4.y, kB.y, fmaf(q4.z, kB.z, q4.w * kB.w)));
#pragma unroll
        for (int o = 8; o > 0; o >>= 1) {
            dA += __shfl_xor_sync(0xffffffffu, dA, o);
            dB += __shfl_xor_sync(0xffffffffu, dB, o);
        }
        float exA = __expf(dA * 0.125f);
        float exB = __expf(dB * 0.125f);
        acc.x = fmaf(exA, vA.x, acc.x); acc.y = fmaf(exA, vA.y, acc.y);
        acc.z = fmaf(exA, vA.z, acc.z); acc.w = fmaf(exA, vA.w, acc.w);
        acc.x = fmaf(exB, vB.x, acc.x); acc.y = fmaf(exB, vB.y, acc.y);
        acc.z = fmaf(exB, vB.z, acc.z); acc.w = fmaf(exB, vB.w, acc.w);
        s += exA + exB;
    }
    for (; i + 1 < end; i += 2) {
        int sA = g_sorted_src[i + half];
        float4 kA = ((const float4*)(g_k + (size_t)sA * D))[hl];
        float4 vA = ((const float4*)(g_v + (size_t)sA * D))[hl];
        float dA = fmaf(q4.x, kA.x, fmaf(q4.y, kA.y, fmaf(q4.z, kA.z, q4.w * kA.w)));
#pragma unroll
        for (int o = 8; o > 0; o >>= 1)
            dA += __shfl_xor_sync(0xffffffffu, dA, o);
        float exA = __expf(dA * 0.125f);
        acc.x = fmaf(exA, vA.x, acc.x); acc.y = fmaf(exA, vA.y, acc.y);
        acc.z = fmaf(exA, vA.z, acc.z); acc.w = fmaf(exA, vA.w, acc.w);
        s += exA;
    }
    if (i < end) {  // odd tail: half 1 contributes zero
        int sA = g_sorted_src[i];
        float4 kA = ((const float4*)(g_k + (size_t)sA * D))[hl];
        float4 vA = ((const float4*)(g_v + (size_t)sA * D))[hl];
        float dA = fmaf(q4.x, kA.x, fmaf(q4.y, kA.y, fmaf(q4.z, kA.z, q4.w * kA.w)));
#pragma unroll
        for (int o = 8; o > 0; o >>= 1)
            dA += __shfl_xor_sync(0xffffffffu, dA, o);
        float exA = half ? 0.f : __expf(dA * 0.125f);
        acc.x = fmaf(exA, vA.x, acc.x); acc.y = fmaf(exA, vA.y, acc.y);
        acc.z = fmaf(exA, vA.z, acc.z); acc.w = fmaf(exA, vA.w, acc.w);
        s += exA;
    }

    // combine halves
    acc.x += __shfl_xor_sync(0xffffffffu, acc.x, 16);
    acc.y += __shfl_xor_sync(0xffffffffu, acc.y, 16);
    acc.z += __shfl_xor_sync(0xffffffffu, acc.z, 16);
    acc.w += __shfl_xor_sync(0xffffffffu, acc.w, 16);
    s     += __shfl_xor_sync(0xffffffffu, s, 16);

    float r = 1.0f / (s + 1e-16f);
    float4 sk = ((const float4*)(g_skip + (size_t)dst * D))[hl];
    float4 o;
    o.x = fmaf(acc.x, r, sk.x);
    o.y = fmaf(acc.y, r, sk.y);
    o.z = fmaf(acc.z, r, sk.z);
    o.w = fmaf(acc.w, r, sk.w);
    if (lane < 16)
        ((float4*)(out + (size_t)dst * D))[hl] = o;
}

// ---------------------------------------------------------------------------
extern "C" void kernel_launch(void* const* d_in, const int* in_sizes, int n_in,
                              void* d_out, int out_size) {
    const float* x  = (const float*)d_in[0];
    const int*   ei = (const int*)d_in[1];   // int64 in ref -> delivered int32
    // d_in[2] = edge_type (unused by reference)
    const float* Wq = (const float*)d_in[3];
    const float* bq = (const float*)d_in[4];
    const float* Wk = (const float*)d_in[5];
    const float* bk = (const float*)d_in[6];
    const float* Wv = (const float*)d_in[7];
    const float* bv = (const float*)d_in[8];
    const float* Ws = (const float*)d_in[9];
    const float* bs = (const float*)d_in[10];
    float* out = (float*)d_out;

    int n = in_sizes[0] / D;   // 100000
    int E = in_sizes[2];       // 1200000
    if (n > NN) n = NN;
    if (E > EE) E = EE;

    float *gq, *gk, *gv, *gsk;
    cudaGetSymbolAddress((void**)&gq,  g_q);
    cudaGetSymbolAddress((void**)&gk,  g_k);
    cudaGetSymbolAddress((void**)&gv,  g_v);
    cudaGetSymbolAddress((void**)&gsk, g_skip);

    int nblk = (n + SCH - 1) / SCH;

    // GEMMs first (independent of CSR chain)
    {
        dim3 grid((n + GR - 1) / GR, 4);
        gemm_one<<<grid, 128>>>(x, Wq, bq, Wk, bk, Wv, bv, Ws, bs,
                                gq, gk, gv, gsk, n);
    }

    // CSR build
    zero_counts<<<(n + 255) / 256, 256>>>(n);
    hist_kernel<<<(E / 4 + 255) / 256, 256>>>(ei, E);
    scan1_kernel<<<nblk, 256>>>(n);
    scan23_kernel<<<nblk, 256>>>(n, nblk);
    scatter_kernel<<<(E / 4 + 255) / 256, 256>>>(ei, E);

    // warp-per-dst gather: attention + normalize + skip, single pass
    {
        int warps_per_block = 8;
        int blocks = (n + warps_per_block - 1) / warps_per_block;
        gather_kernel<<<blocks, 256>>>(out, n);
    }
}

// round 8
// speedup vs baseline: 1.2360x; 1.0097x over previous
#include <cuda_runtime.h>

#define NN 100000
#define EE 1200000
#define D  64
#define GR 128     // X rows per GEMM block
#define SCH 1024   // scan chunk (elements per scan block)

// Scratch (device globals: no allocation allowed in kernel_launch)
__device__ float g_q[(size_t)NN * D];
__device__ float g_k[(size_t)NN * D];
__device__ float g_v[(size_t)NN * D];
__device__ float g_skip[(size_t)NN * D];
__device__ int   g_counts[NN];
__device__ int   g_offsets[NN];   // within-chunk exclusive (scan1 output)
__device__ int   g_cursor[NN];    // global offsets; after scatter = segment END
__device__ int   g_partial[128];
__device__ int   g_sorted_src[EE + 8];   // +8: prefetch overread pad

// ---------------------------------------------------------------------------
// packed f32x2 helpers (Blackwell sm_100+)
// ---------------------------------------------------------------------------
__device__ __forceinline__ unsigned long long dup_f32x2(float x) {
    unsigned long long r;
    asm("mov.b64 %0, {%1, %1};" : "=l"(r) : "f"(x));
    return r;
}
__device__ __forceinline__ void fma_f32x2(unsigned long long& acc,
                                          unsigned long long a,
                                          unsigned long long b) {
    asm("fma.rn.f32x2 %0, %1, %2, %3;" : "=l"(acc) : "l"(a), "l"(b), "l"(acc));
}
__device__ __forceinline__ float2 unpack_f32x2(unsigned long long p) {
    float lo, hi;
    asm("mov.b64 {%0, %1}, %2;" : "=f"(lo), "=f"(hi) : "l"(p));
    return make_float2(lo, hi);
}

// ---------------------------------------------------------------------------
// K_GEMM: blockIdx.y in {0..3} selects W/b/Y (q,k,v,skip).
// GR=128 rows x 64 cols per block, 128 threads, 8x8 micro-tile per thread.
// smem: xsT 32768B + ws 16384B = 49152B (== 48KB static limit)
// ---------------------------------------------------------------------------
__global__ void __launch_bounds__(128) gemm_one(
    const float* __restrict__ X,
    const float* __restrict__ Wq, const float* __restrict__ bq,
    const float* __restrict__ Wk, const float* __restrict__ bk,
    const float* __restrict__ Wv, const float* __restrict__ bv,
    const float* __restrict__ Ws, const float* __restrict__ bs,
    float* __restrict__ Yq, float* __restrict__ Yk,
    float* __restrict__ Yv, float* __restrict__ Ys, int n) {
    __shared__ float xsT[D][GR];   // [k][row]
    __shared__ float ws[D][D];

    int tid  = threadIdx.x;
    int row0 = blockIdx.x * GR;

    const float* W; const float* B; float* Y;
    switch (blockIdx.y) {
        case 0:  W = Wq; B = bq; Y = Yq; break;
        case 1:  W = Wk; B = bk; Y = Yk; break;
        case 2:  W = Wv; B = bv; Y = Yv; break;
        default: W = Ws; B = bs; Y = Ys; break;
    }

    for (int i = tid; i < D * D / 4; i += 128)
        ((float4*)ws)[i] = ((const float4*)W)[i];

    {
        int r = tid;
        bool ok = (row0 + r < n);
#pragma unroll
        for (int c4 = 0; c4 < D / 4; c4++) {
            float4 v = make_float4(0.f, 0.f, 0.f, 0.f);
            if (ok)
                v = ((const float4*)X)[(size_t)(row0 + r) * (D / 4) + c4];
            xsT[c4 * 4 + 0][r] = v.x;
            xsT[c4 * 4 + 1][r] = v.y;
            xsT[c4 * 4 + 2][r] = v.z;
            xsT[c4 * 4 + 3][r] = v.w;
        }
    }
    __syncthreads();

    int tr = (tid >> 3) * 8;  // 0..120
    int tc = (tid & 7) * 8;   // 0..56

    unsigned long long acc[8][4];
#pragma unroll
    for (int r = 0; r < 8; r++)
#pragma unroll
        for (int c = 0; c < 4; c++) acc[r][c] = 0ull;

#pragma unroll 4
    for (int kk = 0; kk < D; kk++) {
        float4 xa = *(const float4*)&xsT[kk][tr];
        float4 xb = *(const float4*)&xsT[kk][tr + 4];
        ulonglong2 wA = *(const ulonglong2*)&ws[kk][tc];
        ulonglong2 wB = *(const ulonglong2*)&ws[kk][tc + 4];
        unsigned long long xd[8];
        xd[0] = dup_f32x2(xa.x); xd[1] = dup_f32x2(xa.y);
        xd[2] = dup_f32x2(xa.z); xd[3] = dup_f32x2(xa.w);
        xd[4] = dup_f32x2(xb.x); xd[5] = dup_f32x2(xb.y);
        xd[6] = dup_f32x2(xb.z); xd[7] = dup_f32x2(xb.w);
#pragma unroll
        for (int r = 0; r < 8; r++) {
            fma_f32x2(acc[r][0], xd[r], wA.x);
            fma_f32x2(acc[r][1], xd[r], wA.y);
            fma_f32x2(acc[r][2], xd[r], wB.x);
            fma_f32x2(acc[r][3], xd[r], wB.y);
        }
    }

    float4 bA = ((const float4*)B)[tc / 4];
    float4 bB = ((const float4*)B)[tc / 4 + 1];
#pragma unroll
    for (int r = 0; r < 8; r++) {
        int grow = row0 + tr + r;
        if (grow < n) {
            float2 p0 = unpack_f32x2(acc[r][0]);
            float2 p1 = unpack_f32x2(acc[r][1]);
            float2 p2 = unpack_f32x2(acc[r][2]);
            float2 p3 = unpack_f32x2(acc[r][3]);
            float4 o0 = make_float4(p0.x + bA.x, p0.y + bA.y,
                                    p1.x + bA.z, p1.y + bA.w);
            float4 o1 = make_float4(p2.x + bB.x, p2.y + bB.y,
                                    p3.x + bB.z, p3.y + bB.w);
            ((float4*)(Y + (size_t)grow * D + tc))[0] = o0;
            ((float4*)(Y + (size_t)grow * D + tc))[1] = o1;
        }
    }
}

// ---------------------------------------------------------------------------
// CSR build: (memset) -> histogram -> scan1 -> scan23 -> scatter
// ---------------------------------------------------------------------------
__global__ void hist_kernel(const int* __restrict__ ei, int E) {
    const int4* d4 = (const int4*)(ei + E);
    int n4 = E >> 2;
    for (int i = blockIdx.x * blockDim.x + threadIdx.x; i < n4;
         i += gridDim.x * blockDim.x) {
        int4 v = d4[i];
        atomicAdd(&g_counts[v.x], 1);
        atomicAdd(&g_counts[v.y], 1);
        atomicAdd(&g_counts[v.z], 1);
        atomicAdd(&g_counts[v.w], 1);
    }
    int t = blockIdx.x * blockDim.x + threadIdx.x;
    if (t < (E & 3)) atomicAdd(&g_counts[ei[E + (n4 << 2) + t]], 1);
}

// per-chunk exclusive scan (256 threads, 4 elems/thread)
__global__ void __launch_bounds__(256) scan1_kernel(int n) {
    __shared__ int sdata[256];
    int t    = threadIdx.x;
    int base = blockIdx.x * SCH + t * 4;

    int v[4];
#pragma unroll
    for (int j = 0; j < 4; j++)
        v[j] = (base + j < n) ? g_counts[base + j] : 0;
    int tsum = v[0] + v[1] + v[2] + v[3];

    sdata[t] = tsum;
    __syncthreads();
    for (int off = 1; off < 256; off <<= 1) {
        int x = (t >= off) ? sdata[t - off] : 0;
        __syncthreads();
        sdata[t] += x;
        __syncthreads();
    }
    int excl = sdata[t] - tsum;
    if (t == 255) g_partial[blockIdx.x] = sdata[255];

    int run = excl;
#pragma unroll
    for (int j = 0; j < 4; j++) {
        if (base + j < n) g_offsets[base + j] = run;
        run += v[j];
    }
}

// fused scan2+scan3: every block redundantly scans the (<=128) partials in
// smem, then adds its chunk's base to produce global offsets into g_cursor.
__global__ void __launch_bounds__(256) scan23_kernel(int n, int nblk) {
    __shared__ int sd[128];
    int t = threadIdx.x;
    if (t < 128) {
        int v = (t < nblk) ? g_partial[t] : 0;
        sd[t] = v;
    }
    __syncthreads();
    for (int off = 1; off < 128; off <<= 1) {
        int x = 0;
        if (t < 128 && t >= off) x = sd[t - off];
        __syncthreads();
        if (t < 128) sd[t] += x;
        __syncthreads();
    }
    int chunk = blockIdx.x;
    int cbase = (chunk > 0) ? sd[chunk - 1] : 0;
    int i0 = chunk * SCH;
    for (int i = i0 + t; i < i0 + SCH && i < n; i += 256)
        g_cursor[i] = g_offsets[i] + cbase;
}

__global__ void scatter_kernel(const int* __restrict__ ei, int E) {
    const int4* s4 = (const int4*)ei;
    const int4* d4 = (const int4*)(ei + E);
    int n4 = E >> 2;
    for (int i = blockIdx.x * blockDim.x + threadIdx.x; i < n4;
         i += gridDim.x * blockDim.x) {
        int4 s = s4[i];
        int4 d = d4[i];
        g_sorted_src[atomicAdd(&g_cursor[d.x], 1)] = s.x;
        g_sorted_src[atomicAdd(&g_cursor[d.y], 1)] = s.y;
        g_sorted_src[atomicAdd(&g_cursor[d.z], 1)] = s.z;
        g_sorted_src[atomicAdd(&g_cursor[d.w], 1)] = s.w;
    }
    int t = blockIdx.x * blockDim.x + threadIdx.x;
    if (t < (E & 3)) {
        int e = (n4 << 2) + t;
        g_sorted_src[atomicAdd(&g_cursor[ei[E + e]], 1)] = ei[e];
    }
}

// ---------------------------------------------------------------------------
// K_GATHER: warp-per-destination, half-warp per edge, software-pipelined:
// src indices for the NEXT 4-edge group are prefetched while the current
// group's k/v rows are in flight (breaks the idx->data latency chain).
// After scatter, g_cursor[dst] == segment END; beg = end - counts[dst].
// ---------------------------------------------------------------------------
__global__ void __launch_bounds__(256) gather_kernel(
    float* __restrict__ out, int n) {
    int warp = (blockIdx.x * blockDim.x + threadIdx.x) >> 5;
    int lane = threadIdx.x & 31;
    if (warp >= n) return;

    int dst  = warp;
    int end  = g_cursor[dst];
    int beg  = end - g_counts[dst];
    int half = lane >> 4;   // 0: edges i, 1: edges i+1
    int hl   = lane & 15;   // chunk index within row

    float4 q4 = ((const float4*)(g_q + (size_t)dst * D))[hl];

    float4 acc = make_float4(0.f, 0.f, 0.f, 0.f);
    float  s   = 0.f;

    int i = beg;
    // prefetch initial pair of indices (pad makes overread safe)
    int cA = g_sorted_src[i + half];
    int cB = g_sorted_src[i + 2 + half];

    for (; i + 3 < end; i += 4) {
        int nA = g_sorted_src[i + 4 + half];
        int nB = g_sorted_src[i + 6 + half];
        float4 kA = ((const float4*)(g_k + (size_t)cA * D))[hl];
        float4 kB = ((const float4*)(g_k + (size_t)cB * D))[hl];
        float4 vA = ((const float4*)(g_v + (size_t)cA * D))[hl];
        float4 vB = ((const float4*)(g_v + (size_t)cB * D))[hl];
        float dA = fmaf(q4.x, kA.x, fmaf(q4.y, kA.y, fmaf(q4.z, kA.z, q4.w * kA.w)));
        float dB = fmaf(q4.x, kB.x, fmaf(q4.y, kB.y, fmaf(q4.z, kB.z, q4.w * kB.w)));
#pragma unroll
        for (int o = 8; o > 0; o >>= 1) {
            dA += __shfl_xor_sync(0xffffffffu, dA, o);
            dB += __shfl_xor_sync(0xffffffffu, dB, o);
        }
        float exA = __expf(dA * 0.125f);
        float exB = __expf(dB * 0.125f);
        acc.x = fmaf(exA, vA.x, acc.x); acc.y = fmaf(exA, vA.y, acc.y);
        acc.z = fmaf(exA, vA.z, acc.z); acc.w = fmaf(exA, vA.w, acc.w);
        acc.x = fmaf(exB, vB.x, acc.x); acc.y = fmaf(exB, vB.y, acc.y);
        acc.z = fmaf(exB, vB.z, acc.z); acc.w = fmaf(exB, vB.w, acc.w);
        s += exA + exB;
        cA = nA;
        cB = nB;
    }
    for (; i + 1 < end; i += 2) {
        int sA = g_sorted_src[i + half];
        float4 kA = ((const float4*)(g_k + (size_t)sA * D))[hl];
        float4 vA = ((const float4*)(g_v + (size_t)sA * D))[hl];
        float dA = fmaf(q4.x, kA.x, fmaf(q4.y, kA.y, fmaf(q4.z, kA.z, q4.w * kA.w)));
#pragma unroll
        for (int o = 8; o > 0; o >>= 1)
            dA += __shfl_xor_sync(0xffffffffu, dA, o);
        float exA = __expf(dA * 0.125f);
        acc.x = fmaf(exA, vA.x, acc.x); acc.y = fmaf(exA, vA.y, acc.y);
        acc.z = fmaf(exA, vA.z, acc.z); acc.w = fmaf(exA, vA.w, acc.w);
        s += exA;
    }
    if (i < end) {  // odd tail: half 1 contributes zero
        int sA = g_sorted_src[i];
        float4 kA = ((const float4*)(g_k + (size_t)sA * D))[hl];
        float4 vA = ((const float4*)(g_v + (size_t)sA * D))[hl];
        float dA = fmaf(q4.x, kA.x, fmaf(q4.y, kA.y, fmaf(q4.z, kA.z, q4.w * kA.w)));
#pragma unroll
        for (int o = 8; o > 0; o >>= 1)
            dA += __shfl_xor_sync(0xffffffffu, dA, o);
        float exA = half ? 0.f : __expf(dA * 0.125f);
        acc.x = fmaf(exA, vA.x, acc.x); acc.y = fmaf(exA, vA.y, acc.y);
        acc.z = fmaf(exA, vA.z, acc.z); acc.w = fmaf(exA, vA.w, acc.w);
        s += exA;
    }

    // combine halves
    acc.x += __shfl_xor_sync(0xffffffffu, acc.x, 16);
    acc.y += __shfl_xor_sync(0xffffffffu, acc.y, 16);
    acc.z += __shfl_xor_sync(0xffffffffu, acc.z, 16);
    acc.w += __shfl_xor_sync(0xffffffffu, acc.w, 16);
    s     += __shfl_xor_sync(0xffffffffu, s, 16);

    float r = 1.0f / (s + 1e-16f);
    float4 sk = ((const float4*)(g_skip + (size_t)dst * D))[hl];
    float4 o;
    o.x = fmaf(acc.x, r, sk.x);
    o.y = fmaf(acc.y, r, sk.y);
    o.z = fmaf(acc.z, r, sk.z);
    o.w = fmaf(acc.w, r, sk.w);
    if (lane < 16)
        ((float4*)(out + (size_t)dst * D))[hl] = o;
}

// ---------------------------------------------------------------------------
extern "C" void kernel_launch(void* const* d_in, const int* in_sizes, int n_in,
                              void* d_out, int out_size) {
    const float* x  = (const float*)d_in[0];
    const int*   ei = (const int*)d_in[1];   // int64 in ref -> delivered int32
    // d_in[2] = edge_type (unused by reference)
    const float* Wq = (const float*)d_in[3];
    const float* bq = (const float*)d_in[4];
    const float* Wk = (const float*)d_in[5];
    const float* bk = (const float*)d_in[6];
    const float* Wv = (const float*)d_in[7];
    const float* bv = (const float*)d_in[8];
    const float* Ws = (const float*)d_in[9];
    const float* bs = (const float*)d_in[10];
    float* out = (float*)d_out;

    int n = in_sizes[0] / D;   // 100000
    int E = in_sizes[2];       // 1200000
    if (n > NN) n = NN;
    if (E > EE) E = EE;

    float *gq, *gk, *gv, *gsk;
    int*  gcnt;
    cudaGetSymbolAddress((void**)&gq,   g_q);
    cudaGetSymbolAddress((void**)&gk,   g_k);
    cudaGetSymbolAddress((void**)&gv,   g_v);
    cudaGetSymbolAddress((void**)&gsk,  g_skip);
    cudaGetSymbolAddress((void**)&gcnt, g_counts);

    int nblk = (n + SCH - 1) / SCH;

    // CSR build
    cudaMemsetAsync(gcnt, 0, (size_t)n * sizeof(int));
    hist_kernel<<<(E / 4 + 255) / 256, 256>>>(ei, E);
    scan1_kernel<<<nblk, 256>>>(n);
    scan23_kernel<<<nblk, 256>>>(n, nblk);
    scatter_kernel<<<(E / 4 + 255) / 256, 256>>>(ei, E);

    // GEMMs: blockIdx.y selects q/k/v/skip
    {
        dim3 grid((n + GR - 1) / GR, 4);
        gemm_one<<<grid, 128>>>(x, Wq, bq, Wk, bk, Wv, bv, Ws, bs,
                                gq, gk, gv, gsk, n);
    }

    // warp-per-dst gather: attention + normalize + skip, single pass
    {
        int warps_per_block = 8;
        int blocks = (n + warps_per_block - 1) / warps_per_block;
        gather_kernel<<<blocks, 256>>>(out, n);
    }
}

// round 9
// speedup vs baseline: 1.2592x; 1.0188x over previous
#include <cuda_runtime.h>

#define NN 100000
#define EE 1200000
#define D  64
#define GR 128     // X rows per GEMM block
#define SCH 1024   // scan chunk (elements per scan block)

// Scratch (device globals: no allocation allowed in kernel_launch)
__device__ float g_q[(size_t)NN * D];
__device__ float g_k[(size_t)NN * D];
__device__ float g_v[(size_t)NN * D];
__device__ float g_skip[(size_t)NN * D];
__device__ int   g_counts[NN];
__device__ int   g_offsets[NN];   // within-chunk exclusive (scan1 output)
__device__ int   g_cursor[NN];    // global offsets; after scatter = segment END
__device__ int   g_partial[128];
__device__ int   g_sorted_src[EE + 16];  // pad: prefetch overread safety

// ---------------------------------------------------------------------------
// packed f32x2 helpers (Blackwell sm_100+)
// ---------------------------------------------------------------------------
__device__ __forceinline__ unsigned long long dup_f32x2(float x) {
    unsigned long long r;
    asm("mov.b64 %0, {%1, %1};" : "=l"(r) : "f"(x));
    return r;
}
__device__ __forceinline__ void fma_f32x2(unsigned long long& acc,
                                          unsigned long long a,
                                          unsigned long long b) {
    asm("fma.rn.f32x2 %0, %1, %2, %3;" : "=l"(acc) : "l"(a), "l"(b), "l"(acc));
}
__device__ __forceinline__ float2 unpack_f32x2(unsigned long long p) {
    float lo, hi;
    asm("mov.b64 {%0, %1}, %2;" : "=f"(lo), "=f"(hi) : "l"(p));
    return make_float2(lo, hi);
}

// ---------------------------------------------------------------------------
// K_GEMM: blockIdx.y in {0..3} selects W/b/Y (q,k,v,skip).
// GR=128 rows x 64 cols per block, 128 threads, 8x8 micro-tile per thread.
// smem: xsT 32768B + ws 16384B = 49152B (== 48KB static limit)
// ---------------------------------------------------------------------------
__global__ void __launch_bounds__(128) gemm_one(
    const float* __restrict__ X,
    const float* __restrict__ Wq, const float* __restrict__ bq,
    const float* __restrict__ Wk, const float* __restrict__ bk,
    const float* __restrict__ Wv, const float* __restrict__ bv,
    const float* __restrict__ Ws, const float* __restrict__ bs,
    float* __restrict__ Yq, float* __restrict__ Yk,
    float* __restrict__ Yv, float* __restrict__ Ys, int n) {
    __shared__ float xsT[D][GR];   // [k][row]
    __shared__ float ws[D][D];

    int tid  = threadIdx.x;
    int row0 = blockIdx.x * GR;

    const float* W; const float* B; float* Y;
    switch (blockIdx.y) {
        case 0:  W = Wq; B = bq; Y = Yq; break;
        case 1:  W = Wk; B = bk; Y = Yk; break;
        case 2:  W = Wv; B = bv; Y = Yv; break;
        default: W = Ws; B = bs; Y = Ys; break;
    }

    for (int i = tid; i < D * D / 4; i += 128)
        ((float4*)ws)[i] = ((const float4*)W)[i];

    {
        int r = tid;
        bool ok = (row0 + r < n);
#pragma unroll
        for (int c4 = 0; c4 < D / 4; c4++) {
            float4 v = make_float4(0.f, 0.f, 0.f, 0.f);
            if (ok)
                v = ((const float4*)X)[(size_t)(row0 + r) * (D / 4) + c4];
            xsT[c4 * 4 + 0][r] = v.x;
            xsT[c4 * 4 + 1][r] = v.y;
            xsT[c4 * 4 + 2][r] = v.z;
            xsT[c4 * 4 + 3][r] = v.w;
        }
    }
    __syncthreads();

    int tr = (tid >> 3) * 8;  // 0..120
    int tc = (tid & 7) * 8;   // 0..56

    unsigned long long acc[8][4];
#pragma unroll
    for (int r = 0; r < 8; r++)
#pragma unroll
        for (int c = 0; c < 4; c++) acc[r][c] = 0ull;

#pragma unroll 4
    for (int kk = 0; kk < D; kk++) {
        float4 xa = *(const float4*)&xsT[kk][tr];
        float4 xb = *(const float4*)&xsT[kk][tr + 4];
        ulonglong2 wA = *(const ulonglong2*)&ws[kk][tc];
        ulonglong2 wB = *(const ulonglong2*)&ws[kk][tc + 4];
        unsigned long long xd[8];
        xd[0] = dup_f32x2(xa.x); xd[1] = dup_f32x2(xa.y);
        xd[2] = dup_f32x2(xa.z); xd[3] = dup_f32x2(xa.w);
        xd[4] = dup_f32x2(xb.x); xd[5] = dup_f32x2(xb.y);
        xd[6] = dup_f32x2(xb.z); xd[7] = dup_f32x2(xb.w);
#pragma unroll
        for (int r = 0; r < 8; r++) {
            fma_f32x2(acc[r][0], xd[r], wA.x);
            fma_f32x2(acc[r][1], xd[r], wA.y);
            fma_f32x2(acc[r][2], xd[r], wB.x);
            fma_f32x2(acc[r][3], xd[r], wB.y);
        }
    }

    float4 bA = ((const float4*)B)[tc / 4];
    float4 bB = ((const float4*)B)[tc / 4 + 1];
#pragma unroll
    for (int r = 0; r < 8; r++) {
        int grow = row0 + tr + r;
        if (grow < n) {
            float2 p0 = unpack_f32x2(acc[r][0]);
            float2 p1 = unpack_f32x2(acc[r][1]);
            float2 p2 = unpack_f32x2(acc[r][2]);
            float2 p3 = unpack_f32x2(acc[r][3]);
            float4 o0 = make_float4(p0.x + bA.x, p0.y + bA.y,
                                    p1.x + bA.z, p1.y + bA.w);
            float4 o1 = make_float4(p2.x + bB.x, p2.y + bB.y,
                                    p3.x + bB.z, p3.y + bB.w);
            ((float4*)(Y + (size_t)grow * D + tc))[0] = o0;
            ((float4*)(Y + (size_t)grow * D + tc))[1] = o1;
        }
    }
}

// ---------------------------------------------------------------------------
// CSR build: (memset) -> histogram -> scan1 -> scan23 -> scatter
// ---------------------------------------------------------------------------
__global__ void hist_kernel(const int* __restrict__ ei, int E) {
    const int4* d4 = (const int4*)(ei + E);
    int n4 = E >> 2;
    for (int i = blockIdx.x * blockDim.x + threadIdx.x; i < n4;
         i += gridDim.x * blockDim.x) {
        int4 v = d4[i];
        atomicAdd(&g_counts[v.x], 1);
        atomicAdd(&g_counts[v.y], 1);
        atomicAdd(&g_counts[v.z], 1);
        atomicAdd(&g_counts[v.w], 1);
    }
    int t = blockIdx.x * blockDim.x + threadIdx.x;
    if (t < (E & 3)) atomicAdd(&g_counts[ei[E + (n4 << 2) + t]], 1);
}

// per-chunk exclusive scan (256 threads, 4 elems/thread)
__global__ void __launch_bounds__(256) scan1_kernel(int n) {
    __shared__ int sdata[256];
    int t    = threadIdx.x;
    int base = blockIdx.x * SCH + t * 4;

    int v[4];
#pragma unroll
    for (int j = 0; j < 4; j++)
        v[j] = (base + j < n) ? g_counts[base + j] : 0;
    int tsum = v[0] + v[1] + v[2] + v[3];

    sdata[t] = tsum;
    __syncthreads();
    for (int off = 1; off < 256; off <<= 1) {
        int x = (t >= off) ? sdata[t - off] : 0;
        __syncthreads();
        sdata[t] += x;
        __syncthreads();
    }
    int excl = sdata[t] - tsum;
    if (t == 255) g_partial[blockIdx.x] = sdata[255];

    int run = excl;
#pragma unroll
    for (int j = 0; j < 4; j++) {
        if (base + j < n) g_offsets[base + j] = run;
        run += v[j];
    }
}

// fused scan2+scan3: every block redundantly scans the (<=128) partials in
// smem, then adds its chunk's base to produce global offsets into g_cursor.
__global__ void __launch_bounds__(256) scan23_kernel(int n, int nblk) {
    __shared__ int sd[128];
    int t = threadIdx.x;
    if (t < 128) {
        int v = (t < nblk) ? g_partial[t] : 0;
        sd[t] = v;
    }
    __syncthreads();
    for (int off = 1; off < 128; off <<= 1) {
        int x = 0;
        if (t < 128 && t >= off) x = sd[t - off];
        __syncthreads();
        if (t < 128) sd[t] += x;
        __syncthreads();
    }
    int chunk = blockIdx.x;
    int cbase = (chunk > 0) ? sd[chunk - 1] : 0;
    int i0 = chunk * SCH;
    for (int i = i0 + t; i < i0 + SCH && i < n; i += 256)
        g_cursor[i] = g_offsets[i] + cbase;
}

__global__ void scatter_kernel(const int* __restrict__ ei, int E) {
    const int4* s4 = (const int4*)ei;
    const int4* d4 = (const int4*)(ei + E);
    int n4 = E >> 2;
    for (int i = blockIdx.x * blockDim.x + threadIdx.x; i < n4;
         i += gridDim.x * blockDim.x) {
        int4 s = s4[i];
        int4 d = d4[i];
        g_sorted_src[atomicAdd(&g_cursor[d.x], 1)] = s.x;
        g_sorted_src[atomicAdd(&g_cursor[d.y], 1)] = s.y;
        g_sorted_src[atomicAdd(&g_cursor[d.z], 1)] = s.z;
        g_sorted_src[atomicAdd(&g_cursor[d.w], 1)] = s.w;
    }
    int t = blockIdx.x * blockDim.x + threadIdx.x;
    if (t < (E & 3)) {
        int e = (n4 << 2) + t;
        g_sorted_src[atomicAdd(&g_cursor[ei[E + e]], 1)] = ei[e];
    }
}

// ---------------------------------------------------------------------------
// K_GATHER: warp-per-destination, half-warp per edge, 6 edges in flight.
// After scatter, g_cursor[dst] == segment END; beg = end - counts[dst].
// ---------------------------------------------------------------------------
__global__ void __launch_bounds__(256) gather_kernel(
    float* __restrict__ out, int n) {
    int warp = (blockIdx.x * blockDim.x + threadIdx.x) >> 5;
    int lane = threadIdx.x & 31;
    if (warp >= n) return;

    int dst  = warp;
    int end  = g_cursor[dst];
    int beg  = end - g_counts[dst];
    int half = lane >> 4;   // which edge of the pair this half-warp takes
    int hl   = lane & 15;   // chunk index within row

    float4 q4 = ((const float4*)(g_q + (size_t)dst * D))[hl];

    float4 acc = make_float4(0.f, 0.f, 0.f, 0.f);
    float  s   = 0.f;

    int i = beg;
    // 6 edges per iteration (3 per half-warp) for deeper MLP
    for (; i + 5 < end; i += 6) {
        int sA = g_sorted_src[i + half];
        int sB = g_sorted_src[i + 2 + half];
        int sC = g_sorted_src[i + 4 + half];
        float4 kA = ((const float4*)(g_k + (size_t)sA * D))[hl];
        float4 kB = ((const float4*)(g_k + (size_t)sB * D))[hl];
        float4 kC = ((const float4*)(g_k + (size_t)sC * D))[hl];
        float4 vA = ((const float4*)(g_v + (size_t)sA * D))[hl];
        float4 vB = ((const float4*)(g_v + (size_t)sB * D))[hl];
        float4 vC = ((const float4*)(g_v + (size_t)sC * D))[hl];
        float dA = fmaf(q4.x, kA.x, fmaf(q4.y, kA.y, fmaf(q4.z, kA.z, q4.w * kA.w)));
        float dB = fmaf(q4.x, kB.x, fmaf(q4.y, kB.y, fmaf(q4.z, kB.z, q4.w * kB.w)));
        float dC = fmaf(q4.x, kC.x, fmaf(q4.y, kC.y, fmaf(q4.z, kC.z, q4.w * kC.w)));
#pragma unroll
        for (int o = 8; o > 0; o >>= 1) {
            dA += __shfl_xor_sync(0xffffffffu, dA, o);
            dB += __shfl_xor_sync(0xffffffffu, dB, o);
            dC += __shfl_xor_sync(0xffffffffu, dC, o);
        }
        float exA = __expf(dA * 0.125f);
        float exB = __expf(dB * 0.125f);
        float exC = __expf(dC * 0.125f);
        acc.x = fmaf(exA, vA.x, acc.x); acc.y = fmaf(exA, vA.y, acc.y);
        acc.z = fmaf(exA, vA.z, acc.z); acc.w = fmaf(exA, vA.w, acc.w);
        acc.x = fmaf(exB, vB.x, acc.x); acc.y = fmaf(exB, vB.y, acc.y);
        acc.z = fmaf(exB, vB.z, acc.z); acc.w = fmaf(exB, vB.w, acc.w);
        acc.x = fmaf(exC, vC.x, acc.x); acc.y = fmaf(exC, vC.y, acc.y);
        acc.z = fmaf(exC, vC.z, acc.z); acc.w = fmaf(exC, vC.w, acc.w);
        s += exA + exB + exC;
    }
    for (; i + 1 < end; i += 2) {
        int sA = g_sorted_src[i + half];
        float4 kA = ((const float4*)(g_k + (size_t)sA * D))[hl];
        float4 vA = ((const float4*)(g_v + (size_t)sA * D))[hl];
        float dA = fmaf(q4.x, kA.x, fmaf(q4.y, kA.y, fmaf(q4.z, kA.z, q4.w * kA.w)));
#pragma unroll
        for (int o = 8; o > 0; o >>= 1)
            dA += __shfl_xor_sync(0xffffffffu, dA, o);
        float exA = __expf(dA * 0.125f);
        acc.x = fmaf(exA, vA.x, acc.x); acc.y = fmaf(exA, vA.y, acc.y);
        acc.z = fmaf(exA, vA.z, acc.z); acc.w = fmaf(exA, vA.w, acc.w);
        s += exA;
    }
    if (i < end) {  // odd tail: half 1 contributes zero
        int sA = g_sorted_src[i];
        float4 kA = ((const float4*)(g_k + (size_t)sA * D))[hl];
        float4 vA = ((const float4*)(g_v + (size_t)sA * D))[hl];
        float dA = fmaf(q4.x, kA.x, fmaf(q4.y, kA.y, fmaf(q4.z, kA.z, q4.w * kA.w)));
#pragma unroll
        for (int o = 8; o > 0; o >>= 1)
            dA += __shfl_xor_sync(0xffffffffu, dA, o);
        float exA = half ? 0.f : __expf(dA * 0.125f);
        acc.x = fmaf(exA, vA.x, acc.x); acc.y = fmaf(exA, vA.y, acc.y);
        acc.z = fmaf(exA, vA.z, acc.z); acc.w = fmaf(exA, vA.w, acc.w);
        s += exA;
    }

    // combine halves
    acc.x += __shfl_xor_sync(0xffffffffu, acc.x, 16);
    acc.y += __shfl_xor_sync(0xffffffffu, acc.y, 16);
    acc.z += __shfl_xor_sync(0xffffffffu, acc.z, 16);
    acc.w += __shfl_xor_sync(0xffffffffu, acc.w, 16);
    s     += __shfl_xor_sync(0xffffffffu, s, 16);

    float r = 1.0f / (s + 1e-16f);
    float4 sk = ((const float4*)(g_skip + (size_t)dst * D))[hl];
    float4 o;
    o.x = fmaf(acc.x, r, sk.x);
    o.y = fmaf(acc.y, r, sk.y);
    o.z = fmaf(acc.z, r, sk.z);
    o.w = fmaf(acc.w, r, sk.w);
    if (lane < 16)
        ((float4*)(out + (size_t)dst * D))[hl] = o;
}

// ---------------------------------------------------------------------------
extern "C" void kernel_launch(void* const* d_in, const int* in_sizes, int n_in,
                              void* d_out, int out_size) {
    const float* x  = (const float*)d_in[0];
    const int*   ei = (const int*)d_in[1];   // int64 in ref -> delivered int32
    // d_in[2] = edge_type (unused by reference)
    const float* Wq = (const float*)d_in[3];
    const float* bq = (const float*)d_in[4];
    const float* Wk = (const float*)d_in[5];
    const float* bk = (const float*)d_in[6];
    const float* Wv = (const float*)d_in[7];
    const float* bv = (const float*)d_in[8];
    const float* Ws = (const float*)d_in[9];
    const float* bs = (const float*)d_in[10];
    float* out = (float*)d_out;

    int n = in_sizes[0] / D;   // 100000
    int E = in_sizes[2];       // 1200000
    if (n > NN) n = NN;
    if (E > EE) E = EE;

    float *gq, *gk, *gv, *gsk;
    int*  gcnt;
    cudaGetSymbolAddress((void**)&gq,   g_q);
    cudaGetSymbolAddress((void**)&gk,   g_k);
    cudaGetSymbolAddress((void**)&gv,   g_v);
    cudaGetSymbolAddress((void**)&gsk,  g_skip);
    cudaGetSymbolAddress((void**)&gcnt, g_counts);

    int nblk = (n + SCH - 1) / SCH;

    // Lazy one-time stream/event creation (host resources only; happens on
    // the uncaptured correctness call, reused identically during capture).
    static cudaStream_t s_side = nullptr;
    static cudaEvent_t  ev_fork = nullptr, ev_join = nullptr;
    if (s_side == nullptr) {
        cudaStreamCreateWithFlags(&s_side, cudaStreamNonBlocking);
        cudaEventCreateWithFlags(&ev_fork, cudaEventDisableTiming);
        cudaEventCreateWithFlags(&ev_join, cudaEventDisableTiming);
    }

    // ---- fork: GEMM on side stream, concurrent with CSR build ----
    cudaEventRecord(ev_fork, 0);
    cudaStreamWaitEvent(s_side, ev_fork, 0);
    {
        dim3 grid((n + GR - 1) / GR, 4);
        gemm_one<<<grid, 128, 0, s_side>>>(x, Wq, bq, Wk, bk, Wv, bv, Ws, bs,
                                           gq, gk, gv, gsk, n);
    }
    cudaEventRecord(ev_join, s_side);

    // ---- CSR build on default stream ----
    cudaMemsetAsync(gcnt, 0, (size_t)n * sizeof(int));
    hist_kernel<<<(E / 4 + 255) / 256, 256>>>(ei, E);
    scan1_kernel<<<nblk, 256>>>(n);
    scan23_kernel<<<nblk, 256>>>(n, nblk);
    scatter_kernel<<<(E / 4 + 255) / 256, 256>>>(ei, E);

    // ---- join, then gather ----
    cudaStreamWaitEvent(0, ev_join, 0);
    {
        int warps_per_block = 8;
        int blocks = (n + warps_per_block - 1) / warps_per_block;
        gather_kernel<<<blocks, 256>>>(out, n);
    }
}

// round 10
// speedup vs baseline: 1.3124x; 1.0423x over previous
#include <cuda_runtime.h>
#include <cuda_bf16.h>

#define NN 100000
#define EE 1200000
#define D  64
#define GR 128     // X rows per GEMM block
#define SCH 1024   // scan chunk (elements per scan block)

// Scratch (device globals: no allocation allowed in kernel_launch)
__device__ float          g_q[(size_t)NN * D];
__device__ __nv_bfloat16  g_kbf[(size_t)NN * D];   // K in bf16 (logits only)
__device__ float          g_v[(size_t)NN * D];
__device__ float          g_skip[(size_t)NN * D];
__device__ int   g_counts[NN];
__device__ int   g_offsets[NN];
__device__ int   g_cursor[NN];    // after scatter = segment END
__device__ int   g_partial[128];
__device__ int   g_sorted_src[EE + 16];

// ---------------------------------------------------------------------------
// packed f32x2 helpers (Blackwell sm_100+)
// ---------------------------------------------------------------------------
__device__ __forceinline__ unsigned long long dup_f32x2(float x) {
    unsigned long long r;
    asm("mov.b64 %0, {%1, %1};" : "=l"(r) : "f"(x));
    return r;
}
__device__ __forceinline__ void fma_f32x2(unsigned long long& acc,
                                          unsigned long long a,
                                          unsigned long long b) {
    asm("fma.rn.f32x2 %0, %1, %2, %3;" : "=l"(acc) : "l"(a), "l"(b), "l"(acc));
}
__device__ __forceinline__ float2 unpack_f32x2(unsigned long long p) {
    float lo, hi;
    asm("mov.b64 {%0, %1}, %2;" : "=f"(lo), "=f"(hi) : "l"(p));
    return make_float2(lo, hi);
}

// ---------------------------------------------------------------------------
// K_GEMM: blockIdx.y in {0..3} selects W/b/Y (q,k,v,skip).
// y==1 (K) stores bf16; others fp32.
// ---------------------------------------------------------------------------
__global__ void __launch_bounds__(128) gemm_one(
    const float* __restrict__ X,
    const float* __restrict__ Wq, const float* __restrict__ bq,
    const float* __restrict__ Wk, const float* __restrict__ bk,
    const float* __restrict__ Wv, const float* __restrict__ bv,
    const float* __restrict__ Ws, const float* __restrict__ bs,
    float* __restrict__ Yq, __nv_bfloat16* __restrict__ Ykb,
    float* __restrict__ Yv, float* __restrict__ Ys, int n) {
    __shared__ float xsT[D][GR];   // [k][row]
    __shared__ float ws[D][D];

    int tid  = threadIdx.x;
    int row0 = blockIdx.x * GR;

    const float* W; const float* B; float* Y;
    switch (blockIdx.y) {
        case 0:  W = Wq; B = bq; Y = Yq; break;
        case 1:  W = Wk; B = bk; Y = nullptr; break;
        case 2:  W = Wv; B = bv; Y = Yv; break;
        default: W = Ws; B = bs; Y = Ys; break;
    }

    for (int i = tid; i < D * D / 4; i += 128)
        ((float4*)ws)[i] = ((const float4*)W)[i];

    {
        int r = tid;
        bool ok = (row0 + r < n);
#pragma unroll
        for (int c4 = 0; c4 < D / 4; c4++) {
            float4 v = make_float4(0.f, 0.f, 0.f, 0.f);
            if (ok)
                v = ((const float4*)X)[(size_t)(row0 + r) * (D / 4) + c4];
            xsT[c4 * 4 + 0][r] = v.x;
            xsT[c4 * 4 + 1][r] = v.y;
            xsT[c4 * 4 + 2][r] = v.z;
            xsT[c4 * 4 + 3][r] = v.w;
        }
    }
    __syncthreads();

    int tr = (tid >> 3) * 8;  // 0..120
    int tc = (tid & 7) * 8;   // 0..56

    unsigned long long acc[8][4];
#pragma unroll
    for (int r = 0; r < 8; r++)
#pragma unroll
        for (int c = 0; c < 4; c++) acc[r][c] = 0ull;

#pragma unroll 4
    for (int kk = 0; kk < D; kk++) {
        float4 xa = *(const float4*)&xsT[kk][tr];
        float4 xb = *(const float4*)&xsT[kk][tr + 4];
        ulonglong2 wA = *(const ulonglong2*)&ws[kk][tc];
        ulonglong2 wB = *(const ulonglong2*)&ws[kk][tc + 4];
        unsigned long long xd[8];
        xd[0] = dup_f32x2(xa.x); xd[1] = dup_f32x2(xa.y);
        xd[2] = dup_f32x2(xa.z); xd[3] = dup_f32x2(xa.w);
        xd[4] = dup_f32x2(xb.x); xd[5] = dup_f32x2(xb.y);
        xd[6] = dup_f32x2(xb.z); xd[7] = dup_f32x2(xb.w);
#pragma unroll
        for (int r = 0; r < 8; r++) {
            fma_f32x2(acc[r][0], xd[r], wA.x);
            fma_f32x2(acc[r][1], xd[r], wA.y);
            fma_f32x2(acc[r][2], xd[r], wB.x);
            fma_f32x2(acc[r][3], xd[r], wB.y);
        }
    }

    float4 bA = ((const float4*)B)[tc / 4];
    float4 bB = ((const float4*)B)[tc / 4 + 1];
    bool is_k = (blockIdx.y == 1);
#pragma unroll
    for (int r = 0; r < 8; r++) {
        int grow = row0 + tr + r;
        if (grow < n) {
            float2 p0 = unpack_f32x2(acc[r][0]);
            float2 p1 = unpack_f32x2(acc[r][1]);
            float2 p2 = unpack_f32x2(acc[r][2]);
            float2 p3 = unpack_f32x2(acc[r][3]);
            float4 o0 = make_float4(p0.x + bA.x, p0.y + bA.y,
                                    p1.x + bA.z, p1.y + bA.w);
            float4 o1 = make_float4(p2.x + bB.x, p2.y + bB.y,
                                    p3.x + bB.z, p3.y + bB.w);
            if (is_k) {
                __nv_bfloat162 pk[4];
                pk[0] = __floats2bfloat162_rn(o0.x, o0.y);
                pk[1] = __floats2bfloat162_rn(o0.z, o0.w);
                pk[2] = __floats2bfloat162_rn(o1.x, o1.y);
                pk[3] = __floats2bfloat162_rn(o1.z, o1.w);
                *((uint4*)(Ykb + (size_t)grow * D + tc)) = *(const uint4*)pk;
            } else {
                ((float4*)(Y + (size_t)grow * D + tc))[0] = o0;
                ((float4*)(Y + (size_t)grow * D + tc))[1] = o1;
            }
        }
    }
}

// ---------------------------------------------------------------------------
// CSR build: (memset) -> histogram -> scan1 -> scan23 -> scatter
// ---------------------------------------------------------------------------
__global__ void hist_kernel(const int* __restrict__ ei, int E) {
    const int4* d4 = (const int4*)(ei + E);
    int n4 = E >> 2;
    for (int i = blockIdx.x * blockDim.x + threadIdx.x; i < n4;
         i += gridDim.x * blockDim.x) {
        int4 v = d4[i];
        atomicAdd(&g_counts[v.x], 1);
        atomicAdd(&g_counts[v.y], 1);
        atomicAdd(&g_counts[v.z], 1);
        atomicAdd(&g_counts[v.w], 1);
    }
    int t = blockIdx.x * blockDim.x + threadIdx.x;
    if (t < (E & 3)) atomicAdd(&g_counts[ei[E + (n4 << 2) + t]], 1);
}

__global__ void __launch_bounds__(256) scan1_kernel(int n) {
    __shared__ int sdata[256];
    int t    = threadIdx.x;
    int base = blockIdx.x * SCH + t * 4;

    int v[4];
#pragma unroll
    for (int j = 0; j < 4; j++)
        v[j] = (base + j < n) ? g_counts[base + j] : 0;
    int tsum = v[0] + v[1] + v[2] + v[3];

    sdata[t] = tsum;
    __syncthreads();
    for (int off = 1; off < 256; off <<= 1) {
        int x = (t >= off) ? sdata[t - off] : 0;
        __syncthreads();
        sdata[t] += x;
        __syncthreads();
    }
    int excl = sdata[t] - tsum;
    if (t == 255) g_partial[blockIdx.x] = sdata[255];

    int run = excl;
#pragma unroll
    for (int j = 0; j < 4; j++) {
        if (base + j < n) g_offsets[base + j] = run;
        run += v[j];
    }
}

__global__ void __launch_bounds__(256) scan23_kernel(int n, int nblk) {
    __shared__ int sd[128];
    int t = threadIdx.x;
    if (t < 128) {
        int v = (t < nblk) ? g_partial[t] : 0;
        sd[t] = v;
    }
    __syncthreads();
    for (int off = 1; off < 128; off <<= 1) {
        int x = 0;
        if (t < 128 && t >= off) x = sd[t - off];
        __syncthreads();
        if (t < 128) sd[t] += x;
        __syncthreads();
    }
    int chunk = blockIdx.x;
    int cbase = (chunk > 0) ? sd[chunk - 1] : 0;
    int i0 = chunk * SCH;
    for (int i = i0 + t; i < i0 + SCH && i < n; i += 256)
        g_cursor[i] = g_offsets[i] + cbase;
}

__global__ void scatter_kernel(const int* __restrict__ ei, int E) {
    const int4* s4 = (const int4*)ei;
    const int4* d4 = (const int4*)(ei + E);
    int n4 = E >> 2;
    for (int i = blockIdx.x * blockDim.x + threadIdx.x; i < n4;
         i += gridDim.x * blockDim.x) {
        int4 s = s4[i];
        int4 d = d4[i];
        g_sorted_src[atomicAdd(&g_cursor[d.x], 1)] = s.x;
        g_sorted_src[atomicAdd(&g_cursor[d.y], 1)] = s.y;
        g_sorted_src[atomicAdd(&g_cursor[d.z], 1)] = s.z;
        g_sorted_src[atomicAdd(&g_cursor[d.w], 1)] = s.w;
    }
    int t = blockIdx.x * blockDim.x + threadIdx.x;
    if (t < (E & 3)) {
        int e = (n4 << 2) + t;
        g_sorted_src[atomicAdd(&g_cursor[ei[E + e]], 1)] = ei[e];
    }
}

// ---------------------------------------------------------------------------
// K_GATHER: warp-per-destination, half-warp per edge, 6 edges in flight.
// k rows are bf16 (LDG.64/lane), converted to fp32 for the dot.
// q is pre-scaled by 1/8 so exp() takes the raw reduced dot.
// ---------------------------------------------------------------------------
__device__ __forceinline__ float dot_bf16(float4 q4, uint2 kraw) {
    float2 lo = __bfloat1622float2(*(const __nv_bfloat162*)&kraw.x);
    float2 hi = __bfloat1622float2(*(const __nv_bfloat162*)&kraw.y);
    return fmaf(q4.x, lo.x, fmaf(q4.y, lo.y, fmaf(q4.z, hi.x, q4.w * hi.y)));
}

__global__ void __launch_bounds__(256) gather_kernel(
    float* __restrict__ out, int n) {
    int warp = (blockIdx.x * blockDim.x + threadIdx.x) >> 5;
    int lane = threadIdx.x & 31;
    if (warp >= n) return;

    int dst  = warp;
    int end  = g_cursor[dst];
    int beg  = end - g_counts[dst];
    int half = lane >> 4;
    int hl   = lane & 15;

    float4 q4 = ((const float4*)(g_q + (size_t)dst * D))[hl];
    q4.x *= 0.125f; q4.y *= 0.125f; q4.z *= 0.125f; q4.w *= 0.125f;

    const uint2* kb = (const uint2*)g_kbf;   // 4 bf16 per uint2

    float4 acc = make_float4(0.f, 0.f, 0.f, 0.f);
    float  s   = 0.f;

    int i = beg;
    for (; i + 5 < end; i += 6) {
        int sA = g_sorted_src[i + half];
        int sB = g_sorted_src[i + 2 + half];
        int sC = g_sorted_src[i + 4 + half];
        uint2  kA = kb[(size_t)sA * (D / 4) + hl];
        uint2  kB = kb[(size_t)sB * (D / 4) + hl];
        uint2  kC = kb[(size_t)sC * (D / 4) + hl];
        float4 vA = ((const float4*)(g_v + (size_t)sA * D))[hl];
        float4 vB = ((const float4*)(g_v + (size_t)sB * D))[hl];
        float4 vC = ((const float4*)(g_v + (size_t)sC * D))[hl];
        float dA = dot_bf16(q4, kA);
        float dB = dot_bf16(q4, kB);
        float dC = dot_bf16(q4, kC);
#pragma unroll
        for (int o = 8; o > 0; o >>= 1) {
            dA += __shfl_xor_sync(0xffffffffu, dA, o);
            dB += __shfl_xor_sync(0xffffffffu, dB, o);
            dC += __shfl_xor_sync(0xffffffffu, dC, o);
        }
        float exA = __expf(dA);
        float exB = __expf(dB);
        float exC = __expf(dC);
        acc.x = fmaf(exA, vA.x, acc.x); acc.y = fmaf(exA, vA.y, acc.y);
        acc.z = fmaf(exA, vA.z, acc.z); acc.w = fmaf(exA, vA.w, acc.w);
        acc.x = fmaf(exB, vB.x, acc.x); acc.y = fmaf(exB, vB.y, acc.y);
        acc.z = fmaf(exB, vB.z, acc.z); acc.w = fmaf(exB, vB.w, acc.w);
        acc.x = fmaf(exC, vC.x, acc.x); acc.y = fmaf(exC, vC.y, acc.y);
        acc.z = fmaf(exC, vC.z, acc.z); acc.w = fmaf(exC, vC.w, acc.w);
        s += exA + exB + exC;
    }
    for (; i + 1 < end; i += 2) {
        int sA = g_sorted_src[i + half];
        uint2  kA = kb[(size_t)sA * (D / 4) + hl];
        float4 vA = ((const float4*)(g_v + (size_t)sA * D))[hl];
        float dA = dot_bf16(q4, kA);
#pragma unroll
        for (int o = 8; o > 0; o >>= 1)
            dA += __shfl_xor_sync(0xffffffffu, dA, o);
        float exA = __expf(dA);
        acc.x = fmaf(exA, vA.x, acc.x); acc.y = fmaf(exA, vA.y, acc.y);
        acc.z = fmaf(exA, vA.z, acc.z); acc.w = fmaf(exA, vA.w, acc.w);
        s += exA;
    }
    if (i < end) {
        int sA = g_sorted_src[i];
        uint2  kA = kb[(size_t)sA * (D / 4) + hl];
        float4 vA = ((const float4*)(g_v + (size_t)sA * D))[hl];
        float dA = dot_bf16(q4, kA);
#pragma unroll
        for (int o = 8; o > 0; o >>= 1)
            dA += __shfl_xor_sync(0xffffffffu, dA, o);
        float exA = half ? 0.f : __expf(dA);
        acc.x = fmaf(exA, vA.x, acc.x); acc.y = fmaf(exA, vA.y, acc.y);
        acc.z = fmaf(exA, vA.z, acc.z); acc.w = fmaf(exA, vA.w, acc.w);
        s += exA;
    }

    acc.x += __shfl_xor_sync(0xffffffffu, acc.x, 16);
    acc.y += __shfl_xor_sync(0xffffffffu, acc.y, 16);
    acc.z += __shfl_xor_sync(0xffffffffu, acc.z, 16);
    acc.w += __shfl_xor_sync(0xffffffffu, acc.w, 16);
    s     += __shfl_xor_sync(0xffffffffu, s, 16);

    float r = 1.0f / (s + 1e-16f);
    float4 sk = ((const float4*)(g_skip + (size_t)dst * D))[hl];
    float4 o;
    o.x = fmaf(acc.x, r, sk.x);
    o.y = fmaf(acc.y, r, sk.y);
    o.z = fmaf(acc.z, r, sk.z);
    o.w = fmaf(acc.w, r, sk.w);
    if (lane < 16)
        ((float4*)(out + (size_t)dst * D))[hl] = o;
}

// ---------------------------------------------------------------------------
extern "C" void kernel_launch(void* const* d_in, const int* in_sizes, int n_in,
                              void* d_out, int out_size) {
    const float* x  = (const float*)d_in[0];
    const int*   ei = (const int*)d_in[1];   // int64 in ref -> delivered int32
    // d_in[2] = edge_type (unused by reference)
    const float* Wq = (const float*)d_in[3];
    const float* bq = (const float*)d_in[4];
    const float* Wk = (const float*)d_in[5];
    const float* bk = (const float*)d_in[6];
    const float* Wv = (const float*)d_in[7];
    const float* bv = (const float*)d_in[8];
    const float* Ws = (const float*)d_in[9];
    const float* bs = (const float*)d_in[10];
    float* out = (float*)d_out;

    int n = in_sizes[0] / D;   // 100000
    int E = in_sizes[2];       // 1200000
    if (n > NN) n = NN;
    if (E > EE) E = EE;

    float *gq, *gv, *gsk;
    __nv_bfloat16* gkb;
    int* gcnt;
    cudaGetSymbolAddress((void**)&gq,   g_q);
    cudaGetSymbolAddress((void**)&gkb,  g_kbf);
    cudaGetSymbolAddress((void**)&gv,   g_v);
    cudaGetSymbolAddress((void**)&gsk,  g_skip);
    cudaGetSymbolAddress((void**)&gcnt, g_counts);

    int nblk = (n + SCH - 1) / SCH;

    static cudaStream_t s_side = nullptr;
    static cudaEvent_t  ev_fork = nullptr, ev_join = nullptr;
    if (s_side == nullptr) {
        cudaStreamCreateWithFlags(&s_side, cudaStreamNonBlocking);
        cudaEventCreateWithFlags(&ev_fork, cudaEventDisableTiming);
        cudaEventCreateWithFlags(&ev_join, cudaEventDisableTiming);
    }

    // ---- fork: GEMM on side stream, concurrent with CSR build ----
    cudaEventRecord(ev_fork, 0);
    cudaStreamWaitEvent(s_side, ev_fork, 0);
    {
        dim3 grid((n + GR - 1) / GR, 4);
        gemm_one<<<grid, 128, 0, s_side>>>(x, Wq, bq, Wk, bk, Wv, bv, Ws, bs,
                                           gq, gkb, gv, gsk, n);
    }
    cudaEventRecord(ev_join, s_side);

    // ---- CSR build on default stream ----
    cudaMemsetAsync(gcnt, 0, (size_t)n * sizeof(int));
    hist_kernel<<<(E / 4 + 255) / 256, 256>>>(ei, E);
    scan1_kernel<<<nblk, 256>>>(n);
    scan23_kernel<<<nblk, 256>>>(n, nblk);
    scatter_kernel<<<(E / 4 + 255) / 256, 256>>>(ei, E);

    // ---- join, then gather ----
    cudaStreamWaitEvent(0, ev_join, 0);
    {
        int warps_per_block = 8;
        int blocks = (n + warps_per_block - 1) / warps_per_block;
        gather_kernel<<<blocks, 256>>>(out, n);
    }
}

// round 11
// speedup vs baseline: 1.3397x; 1.0208x over previous
#include <cuda_runtime.h>
#include <cuda_bf16.h>

#define NN 100000
#define EE 1200000
#define D  64
#define GR 128     // X rows per GEMM block
#define SCH 1024   // scan chunk (elements per scan block)

// Scratch (device globals: no allocation allowed in kernel_launch)
__device__ float          g_q[(size_t)NN * D];
__device__ __nv_bfloat16  g_kbf[(size_t)NN * D];   // K in bf16 (logits only)
__device__ float          g_v[(size_t)NN * D];
__device__ float          g_skip[(size_t)NN * D];
__device__ int   g_counts[NN];
__device__ int   g_offsets[NN];
__device__ int   g_cursor[NN];    // after scatter = segment END
__device__ int   g_partial[128];
__device__ int   g_sorted_src[EE + 16];

// ---------------------------------------------------------------------------
// packed f32x2 helpers (Blackwell sm_100+)
// ---------------------------------------------------------------------------
__device__ __forceinline__ unsigned long long dup_f32x2(float x) {
    unsigned long long r;
    asm("mov.b64 %0, {%1, %1};" : "=l"(r) : "f"(x));
    return r;
}
__device__ __forceinline__ void fma_f32x2(unsigned long long& acc,
                                          unsigned long long a,
                                          unsigned long long b) {
    asm("fma.rn.f32x2 %0, %1, %2, %3;" : "=l"(acc) : "l"(a), "l"(b), "l"(acc));
}
__device__ __forceinline__ float2 unpack_f32x2(unsigned long long p) {
    float lo, hi;
    asm("mov.b64 {%0, %1}, %2;" : "=f"(lo), "=f"(hi) : "l"(p));
    return make_float2(lo, hi);
}

// ---------------------------------------------------------------------------
// K_GEMM: blockIdx.y in {0..3} selects W/b/Y (q,k,v,skip).
// y==1 (K) stores bf16; others fp32.
// ---------------------------------------------------------------------------
__global__ void __launch_bounds__(128) gemm_one(
    const float* __restrict__ X,
    const float* __restrict__ Wq, const float* __restrict__ bq,
    const float* __restrict__ Wk, const float* __restrict__ bk,
    const float* __restrict__ Wv, const float* __restrict__ bv,
    const float* __restrict__ Ws, const float* __restrict__ bs,
    float* __restrict__ Yq, __nv_bfloat16* __restrict__ Ykb,
    float* __restrict__ Yv, float* __restrict__ Ys, int n) {
    __shared__ float xsT[D][GR];   // [k][row]
    __shared__ float ws[D][D];

    int tid  = threadIdx.x;
    int row0 = blockIdx.x * GR;

    const float* W; const float* B; float* Y;
    switch (blockIdx.y) {
        case 0:  W = Wq; B = bq; Y = Yq; break;
        case 1:  W = Wk; B = bk; Y = nullptr; break;
        case 2:  W = Wv; B = bv; Y = Yv; break;
        default: W = Ws; B = bs; Y = Ys; break;
    }

    for (int i = tid; i < D * D / 4; i += 128)
        ((float4*)ws)[i] = ((const float4*)W)[i];

    {
        int r = tid;
        bool ok = (row0 + r < n);
#pragma unroll
        for (int c4 = 0; c4 < D / 4; c4++) {
            float4 v = make_float4(0.f, 0.f, 0.f, 0.f);
            if (ok)
                v = ((const float4*)X)[(size_t)(row0 + r) * (D / 4) + c4];
            xsT[c4 * 4 + 0][r] = v.x;
            xsT[c4 * 4 + 1][r] = v.y;
            xsT[c4 * 4 + 2][r] = v.z;
            xsT[c4 * 4 + 3][r] = v.w;
        }
    }
    __syncthreads();

    int tr = (tid >> 3) * 8;  // 0..120
    int tc = (tid & 7) * 8;   // 0..56

    unsigned long long acc[8][4];
#pragma unroll
    for (int r = 0; r < 8; r++)
#pragma unroll
        for (int c = 0; c < 4; c++) acc[r][c] = 0ull;

#pragma unroll 4
    for (int kk = 0; kk < D; kk++) {
        float4 xa = *(const float4*)&xsT[kk][tr];
        float4 xb = *(const float4*)&xsT[kk][tr + 4];
        ulonglong2 wA = *(const ulonglong2*)&ws[kk][tc];
        ulonglong2 wB = *(const ulonglong2*)&ws[kk][tc + 4];
        unsigned long long xd[8];
        xd[0] = dup_f32x2(xa.x); xd[1] = dup_f32x2(xa.y);
        xd[2] = dup_f32x2(xa.z); xd[3] = dup_f32x2(xa.w);
        xd[4] = dup_f32x2(xb.x); xd[5] = dup_f32x2(xb.y);
        xd[6] = dup_f32x2(xb.z); xd[7] = dup_f32x2(xb.w);
#pragma unroll
        for (int r = 0; r < 8; r++) {
            fma_f32x2(acc[r][0], xd[r], wA.x);
            fma_f32x2(acc[r][1], xd[r], wA.y);
            fma_f32x2(acc[r][2], xd[r], wB.x);
            fma_f32x2(acc[r][3], xd[r], wB.y);
        }
    }

    float4 bA = ((const float4*)B)[tc / 4];
    float4 bB = ((const float4*)B)[tc / 4 + 1];
    bool is_k = (blockIdx.y == 1);
#pragma unroll
    for (int r = 0; r < 8; r++) {
        int grow = row0 + tr + r;
        if (grow < n) {
            float2 p0 = unpack_f32x2(acc[r][0]);
            float2 p1 = unpack_f32x2(acc[r][1]);
            float2 p2 = unpack_f32x2(acc[r][2]);
            float2 p3 = unpack_f32x2(acc[r][3]);
            float4 o0 = make_float4(p0.x + bA.x, p0.y + bA.y,
                                    p1.x + bA.z, p1.y + bA.w);
            float4 o1 = make_float4(p2.x + bB.x, p2.y + bB.y,
                                    p3.x + bB.z, p3.y + bB.w);
            if (is_k) {
                __nv_bfloat162 pk[4];
                pk[0] = __floats2bfloat162_rn(o0.x, o0.y);
                pk[1] = __floats2bfloat162_rn(o0.z, o0.w);
                pk[2] = __floats2bfloat162_rn(o1.x, o1.y);
                pk[3] = __floats2bfloat162_rn(o1.z, o1.w);
                *((uint4*)(Ykb + (size_t)grow * D + tc)) = *(const uint4*)pk;
            } else {
                ((float4*)(Y + (size_t)grow * D + tc))[0] = o0;
                ((float4*)(Y + (size_t)grow * D + tc))[1] = o1;
            }
        }
    }
}

// ---------------------------------------------------------------------------
// CSR build: (memset) -> histogram -> scan1 -> scan23 -> scatter
// ---------------------------------------------------------------------------
__global__ void hist_kernel(const int* __restrict__ ei, int E) {
    const int4* d4 = (const int4*)(ei + E);
    int n4 = E >> 2;
    for (int i = blockIdx.x * blockDim.x + threadIdx.x; i < n4;
         i += gridDim.x * blockDim.x) {
        int4 v = d4[i];
        atomicAdd(&g_counts[v.x], 1);
        atomicAdd(&g_counts[v.y], 1);
        atomicAdd(&g_counts[v.z], 1);
        atomicAdd(&g_counts[v.w], 1);
    }
    int t = blockIdx.x * blockDim.x + threadIdx.x;
    if (t < (E & 3)) atomicAdd(&g_counts[ei[E + (n4 << 2) + t]], 1);
}

__global__ void __launch_bounds__(256) scan1_kernel(int n) {
    __shared__ int sdata[256];
    int t    = threadIdx.x;
    int base = blockIdx.x * SCH + t * 4;

    int v[4];
#pragma unroll
    for (int j = 0; j < 4; j++)
        v[j] = (base + j < n) ? g_counts[base + j] : 0;
    int tsum = v[0] + v[1] + v[2] + v[3];

    sdata[t] = tsum;
    __syncthreads();
    for (int off = 1; off < 256; off <<= 1) {
        int x = (t >= off) ? sdata[t - off] : 0;
        __syncthreads();
        sdata[t] += x;
        __syncthreads();
    }
    int excl = sdata[t] - tsum;
    if (t == 255) g_partial[blockIdx.x] = sdata[255];

    int run = excl;
#pragma unroll
    for (int j = 0; j < 4; j++) {
        if (base + j < n) g_offsets[base + j] = run;
        run += v[j];
    }
}

__global__ void __launch_bounds__(256) scan23_kernel(int n, int nblk) {
    __shared__ int sd[128];
    int t = threadIdx.x;
    if (t < 128) {
        int v = (t < nblk) ? g_partial[t] : 0;
        sd[t] = v;
    }
    __syncthreads();
    for (int off = 1; off < 128; off <<= 1) {
        int x = 0;
        if (t < 128 && t >= off) x = sd[t - off];
        __syncthreads();
        if (t < 128) sd[t] += x;
        __syncthreads();
    }
    int chunk = blockIdx.x;
    int cbase = (chunk > 0) ? sd[chunk - 1] : 0;
    int i0 = chunk * SCH;
    for (int i = i0 + t; i < i0 + SCH && i < n; i += 256)
        g_cursor[i] = g_offsets[i] + cbase;
}

__global__ void scatter_kernel(const int* __restrict__ ei, int E) {
    const int4* s4 = (const int4*)ei;
    const int4* d4 = (const int4*)(ei + E);
    int n4 = E >> 2;
    for (int i = blockIdx.x * blockDim.x + threadIdx.x; i < n4;
         i += gridDim.x * blockDim.x) {
        int4 s = s4[i];
        int4 d = d4[i];
        g_sorted_src[atomicAdd(&g_cursor[d.x], 1)] = s.x;
        g_sorted_src[atomicAdd(&g_cursor[d.y], 1)] = s.y;
        g_sorted_src[atomicAdd(&g_cursor[d.z], 1)] = s.z;
        g_sorted_src[atomicAdd(&g_cursor[d.w], 1)] = s.w;
    }
    int t = blockIdx.x * blockDim.x + threadIdx.x;
    if (t < (E & 3)) {
        int e = (n4 << 2) + t;
        g_sorted_src[atomicAdd(&g_cursor[ei[E + e]], 1)] = ei[e];
    }
}

// ---------------------------------------------------------------------------
// K_GATHER: warp-per-destination, half-warp per edge, 6 edges in flight.
// k rows are bf16 (LDG.64/lane), converted to fp32 for the dot.
// q is pre-scaled by 1/8 so exp() takes the raw reduced dot.
// ---------------------------------------------------------------------------
__device__ __forceinline__ float dot_bf16(float4 q4, uint2 kraw) {
    float2 lo = __bfloat1622float2(*(const __nv_bfloat162*)&kraw.x);
    float2 hi = __bfloat1622float2(*(const __nv_bfloat162*)&kraw.y);
    return fmaf(q4.x, lo.x, fmaf(q4.y, lo.y, fmaf(q4.z, hi.x, q4.w * hi.y)));
}

__global__ void __launch_bounds__(256) gather_kernel(
    float* __restrict__ out, int n) {
    int warp = (blockIdx.x * blockDim.x + threadIdx.x) >> 5;
    int lane = threadIdx.x & 31;
    if (warp >= n) return;

    int dst  = warp;
    int end  = g_cursor[dst];
    int beg  = end - g_counts[dst];
    int half = lane >> 4;
    int hl   = lane & 15;

    float4 q4 = ((const float4*)(g_q + (size_t)dst * D))[hl];
    q4.x *= 0.125f; q4.y *= 0.125f; q4.z *= 0.125f; q4.w *= 0.125f;

    const uint2* kb = (const uint2*)g_kbf;   // 4 bf16 per uint2

    float4 acc = make_float4(0.f, 0.f, 0.f, 0.f);
    float  s   = 0.f;

    int i = beg;
    for (; i + 5 < end; i += 6) {
        int sA = g_sorted_src[i + half];
        int sB = g_sorted_src[i + 2 + half];
        int sC = g_sorted_src[i + 4 + half];
        uint2  kA = kb[(size_t)sA * (D / 4) + hl];
        uint2  kB = kb[(size_t)sB * (D / 4) + hl];
        uint2  kC = kb[(size_t)sC * (D / 4) + hl];
        float4 vA = ((const float4*)(g_v + (size_t)sA * D))[hl];
        float4 vB = ((const float4*)(g_v + (size_t)sB * D))[hl];
        float4 vC = ((const float4*)(g_v + (size_t)sC * D))[hl];
        float dA = dot_bf16(q4, kA);
        float dB = dot_bf16(q4, kB);
        float dC = dot_bf16(q4, kC);
#pragma unroll
        for (int o = 8; o > 0; o >>= 1) {
            dA += __shfl_xor_sync(0xffffffffu, dA, o);
            dB += __shfl_xor_sync(0xffffffffu, dB, o);
            dC += __shfl_xor_sync(0xffffffffu, dC, o);
        }
        float exA = __expf(dA);
        float exB = __expf(dB);
        float exC = __expf(dC);
        acc.x = fmaf(exA, vA.x, acc.x); acc.y = fmaf(exA, vA.y, acc.y);
        acc.z = fmaf(exA, vA.z, acc.z); acc.w = fmaf(exA, vA.w, acc.w);
        acc.x = fmaf(exB, vB.x, acc.x); acc.y = fmaf(exB, vB.y, acc.y);
        acc.z = fmaf(exB, vB.z, acc.z); acc.w = fmaf(exB, vB.w, acc.w);
        acc.x = fmaf(exC, vC.x, acc.x); acc.y = fmaf(exC, vC.y, acc.y);
        acc.z = fmaf(exC, vC.z, acc.z); acc.w = fmaf(exC, vC.w, acc.w);
        s += exA + exB + exC;
    }
    for (; i + 1 < end; i += 2) {
        int sA = g_sorted_src[i + half];
        uint2  kA = kb[(size_t)sA * (D / 4) + hl];
        float4 vA = ((const float4*)(g_v + (size_t)sA * D))[hl];
        float dA = dot_bf16(q4, kA);
#pragma unroll
        for (int o = 8; o > 0; o >>= 1)
            dA += __shfl_xor_sync(0xffffffffu, dA, o);
        float exA = __expf(dA);
        acc.x = fmaf(exA, vA.x, acc.x); acc.y = fmaf(exA, vA.y, acc.y);
        acc.z = fmaf(exA, vA.z, acc.z); acc.w = fmaf(exA, vA.w, acc.w);
        s += exA;
    }
    if (i < end) {
        int sA = g_sorted_src[i];
        uint2  kA = kb[(size_t)sA * (D / 4) + hl];
        float4 vA = ((const float4*)(g_v + (size_t)sA * D))[hl];
        float dA = dot_bf16(q4, kA);
#pragma unroll
        for (int o = 8; o > 0; o >>= 1)
            dA += __shfl_xor_sync(0xffffffffu, dA, o);
        float exA = half ? 0.f : __expf(dA);
        acc.x = fmaf(exA, vA.x, acc.x); acc.y = fmaf(exA, vA.y, acc.y);
        acc.z = fmaf(exA, vA.z, acc.z); acc.w = fmaf(exA, vA.w, acc.w);
        s += exA;
    }

    acc.x += __shfl_xor_sync(0xffffffffu, acc.x, 16);
    acc.y += __shfl_xor_sync(0xffffffffu, acc.y, 16);
    acc.z += __shfl_xor_sync(0xffffffffu, acc.z, 16);
    acc.w += __shfl_xor_sync(0xffffffffu, acc.w, 16);
    s     += __shfl_xor_sync(0xffffffffu, s, 16);

    float r = 1.0f / (s + 1e-16f);
    float4 sk = ((const float4*)(g_skip + (size_t)dst * D))[hl];
    float4 o;
    o.x = fmaf(acc.x, r, sk.x);
    o.y = fmaf(acc.y, r, sk.y);
    o.z = fmaf(acc.z, r, sk.z);
    o.w = fmaf(acc.w, r, sk.w);
    if (lane < 16)
        ((float4*)(out + (size_t)dst * D))[hl] = o;
}

// ---------------------------------------------------------------------------
extern "C" void kernel_launch(void* const* d_in, const int* in_sizes, int n_in,
                              void* d_out, int out_size) {
    const float* x  = (const float*)d_in[0];
    const int*   ei = (const int*)d_in[1];   // int64 in ref -> delivered int32
    // d_in[2] = edge_type (unused by reference)
    const float* Wq = (const float*)d_in[3];
    const float* bq = (const float*)d_in[4];
    const float* Wk = (const float*)d_in[5];
    const float* bk = (const float*)d_in[6];
    const float* Wv = (const float*)d_in[7];
    const float* bv = (const float*)d_in[8];
    const float* Ws = (const float*)d_in[9];
    const float* bs = (const float*)d_in[10];
    float* out = (float*)d_out;

    int n = in_sizes[0] / D;   // 100000
    int E = in_sizes[2];       // 1200000
    if (n > NN) n = NN;
    if (E > EE) E = EE;

    float *gq, *gv, *gsk;
    __nv_bfloat16* gkb;
    int* gcnt;
    cudaGetSymbolAddress((void**)&gq,   g_q);
    cudaGetSymbolAddress((void**)&gkb,  g_kbf);
    cudaGetSymbolAddress((void**)&gv,   g_v);
    cudaGetSymbolAddress((void**)&gsk,  g_skip);
    cudaGetSymbolAddress((void**)&gcnt, g_counts);

    int nblk = (n + SCH - 1) / SCH;

    static cudaStream_t s_side = nullptr;
    static cudaEvent_t  ev_fork = nullptr, ev_join = nullptr;
    if (s_side == nullptr) {
        cudaStreamCreateWithFlags(&s_side, cudaStreamNonBlocking);
        cudaEventCreateWithFlags(&ev_fork, cudaEventDisableTiming);
        cudaEventCreateWithFlags(&ev_join, cudaEventDisableTiming);
    }

    // ---- fork: GEMM on side stream, concurrent with CSR build ----
    cudaEventRecord(ev_fork, 0);
    cudaStreamWaitEvent(s_side, ev_fork, 0);
    {
        dim3 grid((n + GR - 1) / GR, 4);
        gemm_one<<<grid, 128, 0, s_side>>>(x, Wq, bq, Wk, bk, Wv, bv, Ws, bs,
                                           gq, gkb, gv, gsk, n);
    }
    cudaEventRecord(ev_join, s_side);

    // ---- CSR build on default stream ----
    cudaMemsetAsync(gcnt, 0, (size_t)n * sizeof(int));
    hist_kernel<<<(E / 4 + 255) / 256, 256>>>(ei, E);
    scan1_kernel<<<nblk, 256>>>(n);
    scan23_kernel<<<nblk, 256>>>(n, nblk);
    scatter_kernel<<<(E / 4 + 255) / 256, 256>>>(ei, E);

    // ---- join, then gather ----
    cudaStreamWaitEvent(0, ev_join, 0);
    {
        int warps_per_block = 8;
        int blocks = (n + warps_per_block - 1) / warps_per_block;
        gather_kernel<<<blocks, 256>>>(out, n);
    }
}

// round 12
// speedup vs baseline: 1.3414x; 1.0013x over previous
#include <cuda_runtime.h>
#include <cuda_bf16.h>

#define NN 100000
#define EE 1200000
#define D  64
#define GR 128     // X rows per GEMM block
#define SCH 1024   // scan chunk (elements per scan block)

// Scratch (device globals: no allocation allowed in kernel_launch)
__device__ float          g_q[(size_t)NN * D];
__device__ __nv_bfloat16  g_kbf[(size_t)NN * D];   // K in bf16 (logits only)
__device__ float          g_v[(size_t)NN * D];
__device__ float          g_skip[(size_t)NN * D];
__device__ int   g_counts[NN];
__device__ int   g_offsets[NN];
__device__ int   g_cursor[NN];    // after scatter = segment END
__device__ int   g_partial[128];
__device__ int   g_sorted_src[EE + 16];

// ---------------------------------------------------------------------------
// packed f32x2 helpers (Blackwell sm_100+)
// ---------------------------------------------------------------------------
__device__ __forceinline__ unsigned long long dup_f32x2(float x) {
    unsigned long long r;
    asm("mov.b64 %0, {%1, %1};" : "=l"(r) : "f"(x));
    return r;
}
__device__ __forceinline__ void fma_f32x2(unsigned long long& acc,
                                          unsigned long long a,
                                          unsigned long long b) {
    asm("fma.rn.f32x2 %0, %1, %2, %3;" : "=l"(acc) : "l"(a), "l"(b), "l"(acc));
}
__device__ __forceinline__ float2 unpack_f32x2(unsigned long long p) {
    float lo, hi;
    asm("mov.b64 {%0, %1}, %2;" : "=f"(lo), "=f"(hi) : "l"(p));
    return make_float2(lo, hi);
}

// ---------------------------------------------------------------------------
// K_GEMM: blockIdx.y in {0..3} selects W/b/Y (q,k,v,skip).
// y==1 (K) stores bf16; others fp32.
// ---------------------------------------------------------------------------
__global__ void __launch_bounds__(128) gemm_one(
    const float* __restrict__ X,
    const float* __restrict__ Wq, const float* __restrict__ bq,
    const float* __restrict__ Wk, const float* __restrict__ bk,
    const float* __restrict__ Wv, const float* __restrict__ bv,
    const float* __restrict__ Ws, const float* __restrict__ bs,
    float* __restrict__ Yq, __nv_bfloat16* __restrict__ Ykb,
    float* __restrict__ Yv, float* __restrict__ Ys, int n) {
    __shared__ float xsT[D][GR];   // [k][row]
    __shared__ float ws[D][D];

    int tid  = threadIdx.x;
    int row0 = blockIdx.x * GR;

    const float* W; const float* B; float* Y;
    switch (blockIdx.y) {
        case 0:  W = Wq; B = bq; Y = Yq; break;
        case 1:  W = Wk; B = bk; Y = nullptr; break;
        case 2:  W = Wv; B = bv; Y = Yv; break;
        default: W = Ws; B = bs; Y = Ys; break;
    }

    for (int i = tid; i < D * D / 4; i += 128)
        ((float4*)ws)[i] = ((const float4*)W)[i];

    {
        int r = tid;
        bool ok = (row0 + r < n);
#pragma unroll
        for (int c4 = 0; c4 < D / 4; c4++) {
            float4 v = make_float4(0.f, 0.f, 0.f, 0.f);
            if (ok)
                v = ((const float4*)X)[(size_t)(row0 + r) * (D / 4) + c4];
            xsT[c4 * 4 + 0][r] = v.x;
            xsT[c4 * 4 + 1][r] = v.y;
            xsT[c4 * 4 + 2][r] = v.z;
            xsT[c4 * 4 + 3][r] = v.w;
        }
    }
    __syncthreads();

    int tr = (tid >> 3) * 8;  // 0..120
    int tc = (tid & 7) * 8;   // 0..56

    unsigned long long acc[8][4];
#pragma unroll
    for (int r = 0; r < 8; r++)
#pragma unroll
        for (int c = 0; c < 4; c++) acc[r][c] = 0ull;

#pragma unroll 4
    for (int kk = 0; kk < D; kk++) {
        float4 xa = *(const float4*)&xsT[kk][tr];
        float4 xb = *(const float4*)&xsT[kk][tr + 4];
        ulonglong2 wA = *(const ulonglong2*)&ws[kk][tc];
        ulonglong2 wB = *(const ulonglong2*)&ws[kk][tc + 4];
        unsigned long long xd[8];
        xd[0] = dup_f32x2(xa.x); xd[1] = dup_f32x2(xa.y);
        xd[2] = dup_f32x2(xa.z); xd[3] = dup_f32x2(xa.w);
        xd[4] = dup_f32x2(xb.x); xd[5] = dup_f32x2(xb.y);
        xd[6] = dup_f32x2(xb.z); xd[7] = dup_f32x2(xb.w);
#pragma unroll
        for (int r = 0; r < 8; r++) {
            fma_f32x2(acc[r][0], xd[r], wA.x);
            fma_f32x2(acc[r][1], xd[r], wA.y);
            fma_f32x2(acc[r][2], xd[r], wB.x);
            fma_f32x2(acc[r][3], xd[r], wB.y);
        }
    }

    float4 bA = ((const float4*)B)[tc / 4];
    float4 bB = ((const float4*)B)[tc / 4 + 1];
    bool is_k = (blockIdx.y == 1);
#pragma unroll
    for (int r = 0; r < 8; r++) {
        int grow = row0 + tr + r;
        if (grow < n) {
            float2 p0 = unpack_f32x2(acc[r][0]);
            float2 p1 = unpack_f32x2(acc[r][1]);
            float2 p2 = unpack_f32x2(acc[r][2]);
            float2 p3 = unpack_f32x2(acc[r][3]);
            float4 o0 = make_float4(p0.x + bA.x, p0.y + bA.y,
                                    p1.x + bA.z, p1.y + bA.w);
            float4 o1 = make_float4(p2.x + bB.x, p2.y + bB.y,
                                    p3.x + bB.z, p3.y + bB.w);
            if (is_k) {
                __nv_bfloat162 pk[4];
                pk[0] = __floats2bfloat162_rn(o0.x, o0.y);
                pk[1] = __floats2bfloat162_rn(o0.z, o0.w);
                pk[2] = __floats2bfloat162_rn(o1.x, o1.y);
                pk[3] = __floats2bfloat162_rn(o1.z, o1.w);
                *((uint4*)(Ykb + (size_t)grow * D + tc)) = *(const uint4*)pk;
            } else {
                ((float4*)(Y + (size_t)grow * D + tc))[0] = o0;
                ((float4*)(Y + (size_t)grow * D + tc))[1] = o1;
            }
        }
    }
}

// ---------------------------------------------------------------------------
// CSR build: (memset) -> histogram -> scan1 -> scan23 -> scatter
// ---------------------------------------------------------------------------
__global__ void hist_kernel(const int* __restrict__ ei, int E) {
    const int4* d4 = (const int4*)(ei + E);
    int n4 = E >> 2;
    for (int i = blockIdx.x * blockDim.x + threadIdx.x; i < n4;
         i += gridDim.x * blockDim.x) {
        int4 v = d4[i];
        atomicAdd(&g_counts[v.x], 1);
        atomicAdd(&g_counts[v.y], 1);
        atomicAdd(&g_counts[v.z], 1);
        atomicAdd(&g_counts[v.w], 1);
    }
    int t = blockIdx.x * blockDim.x + threadIdx.x;
    if (t < (E & 3)) atomicAdd(&g_counts[ei[E + (n4 << 2) + t]], 1);
}

__global__ void __launch_bounds__(256) scan1_kernel(int n) {
    __shared__ int sdata[256];
    int t    = threadIdx.x;
    int base = blockIdx.x * SCH + t * 4;

    int v[4];
#pragma unroll
    for (int j = 0; j < 4; j++)
        v[j] = (base + j < n) ? g_counts[base + j] : 0;
    int tsum = v[0] + v[1] + v[2] + v[3];

    sdata[t] = tsum;
    __syncthreads();
    for (int off = 1; off < 256; off <<= 1) {
        int x = (t >= off) ? sdata[t - off] : 0;
        __syncthreads();
        sdata[t] += x;
        __syncthreads();
    }
    int excl = sdata[t] - tsum;
    if (t == 255) g_partial[blockIdx.x] = sdata[255];

    int run = excl;
#pragma unroll
    for (int j = 0; j < 4; j++) {
        if (base + j < n) g_offsets[base + j] = run;
        run += v[j];
    }
}

__global__ void __launch_bounds__(256) scan23_kernel(int n, int nblk) {
    __shared__ int sd[128];
    int t = threadIdx.x;
    if (t < 128) {
        int v = (t < nblk) ? g_partial[t] : 0;
        sd[t] = v;
    }
    __syncthreads();
    for (int off = 1; off < 128; off <<= 1) {
        int x = 0;
        if (t < 128 && t >= off) x = sd[t - off];
        __syncthreads();
        if (t < 128) sd[t] += x;
        __syncthreads();
    }
    int chunk = blockIdx.x;
    int cbase = (chunk > 0) ? sd[chunk - 1] : 0;
    int i0 = chunk * SCH;
    for (int i = i0 + t; i < i0 + SCH && i < n; i += 256)
        g_cursor[i] = g_offsets[i] + cbase;
}

__global__ void scatter_kernel(const int* __restrict__ ei, int E) {
    const int4* s4 = (const int4*)ei;
    const int4* d4 = (const int4*)(ei + E);
    int n4 = E >> 2;
    for (int i = blockIdx.x * blockDim.x + threadIdx.x; i < n4;
         i += gridDim.x * blockDim.x) {
        int4 s = s4[i];
        int4 d = d4[i];
        g_sorted_src[atomicAdd(&g_cursor[d.x], 1)] = s.x;
        g_sorted_src[atomicAdd(&g_cursor[d.y], 1)] = s.y;
        g_sorted_src[atomicAdd(&g_cursor[d.z], 1)] = s.z;
        g_sorted_src[atomicAdd(&g_cursor[d.w], 1)] = s.w;
    }
    int t = blockIdx.x * blockDim.x + threadIdx.x;
    if (t < (E & 3)) {
        int e = (n4 << 2) + t;
        g_sorted_src[atomicAdd(&g_cursor[ei[E + e]], 1)] = ei[e];
    }
}

// ---------------------------------------------------------------------------
// K_GATHER: warp-per-destination, half-warp per edge, 6 edges in flight.
// k rows are bf16 (LDG.64/lane), converted to fp32 for the dot.
// q is pre-scaled by 1/8 so exp() takes the raw reduced dot.
// ---------------------------------------------------------------------------
__device__ __forceinline__ float dot_bf16(float4 q4, uint2 kraw) {
    float2 lo = __bfloat1622float2(*(const __nv_bfloat162*)&kraw.x);
    float2 hi = __bfloat1622float2(*(const __nv_bfloat162*)&kraw.y);
    return fmaf(q4.x, lo.x, fmaf(q4.y, lo.y, fmaf(q4.z, hi.x, q4.w * hi.y)));
}

__global__ void __launch_bounds__(256) gather_kernel(
    float* __restrict__ out, int n) {
    int warp = (blockIdx.x * blockDim.x + threadIdx.x) >> 5;
    int lane = threadIdx.x & 31;
    if (warp >= n) return;

    int dst  = warp;
    int end  = g_cursor[dst];
    int beg  = end - g_counts[dst];
    int half = lane >> 4;
    int hl   = lane & 15;

    float4 q4 = ((const float4*)(g_q + (size_t)dst * D))[hl];
    q4.x *= 0.125f; q4.y *= 0.125f; q4.z *= 0.125f; q4.w *= 0.125f;

    const uint2* kb = (const uint2*)g_kbf;   // 4 bf16 per uint2

    float4 acc = make_float4(0.f, 0.f, 0.f, 0.f);
    float  s   = 0.f;

    int i = beg;
    for (; i + 5 < end; i += 6) {
        int sA = g_sorted_src[i + half];
        int sB = g_sorted_src[i + 2 + half];
        int sC = g_sorted_src[i + 4 + half];
        uint2  kA = kb[(size_t)sA * (D / 4) + hl];
        uint2  kB = kb[(size_t)sB * (D / 4) + hl];
        uint2  kC = kb[(size_t)sC * (D / 4) + hl];
        float4 vA = ((const float4*)(g_v + (size_t)sA * D))[hl];
        float4 vB = ((const float4*)(g_v + (size_t)sB * D))[hl];
        float4 vC = ((const float4*)(g_v + (size_t)sC * D))[hl];
        float dA = dot_bf16(q4, kA);
        float dB = dot_bf16(q4, kB);
        float dC = dot_bf16(q4, kC);
#pragma unroll
        for (int o = 8; o > 0; o >>= 1) {
            dA += __shfl_xor_sync(0xffffffffu, dA, o);
            dB += __shfl_xor_sync(0xffffffffu, dB, o);
            dC += __shfl_xor_sync(0xffffffffu, dC, o);
        }
        float exA = __expf(dA);
        float exB = __expf(dB);
        float exC = __expf(dC);
        acc.x = fmaf(exA, vA.x, acc.x); acc.y = fmaf(exA, vA.y, acc.y);
        acc.z = fmaf(exA, vA.z, acc.z); acc.w = fmaf(exA, vA.w, acc.w);
        acc.x = fmaf(exB, vB.x, acc.x); acc.y = fmaf(exB, vB.y, acc.y);
        acc.z = fmaf(exB, vB.z, acc.z); acc.w = fmaf(exB, vB.w, acc.w);
        acc.x = fmaf(exC, vC.x, acc.x); acc.y = fmaf(exC, vC.y, acc.y);
        acc.z = fmaf(exC, vC.z, acc.z); acc.w = fmaf(exC, vC.w, acc.w);
        s += exA + exB + exC;
    }
    for (; i + 1 < end; i += 2) {
        int sA = g_sorted_src[i + half];
        uint2  kA = kb[(size_t)sA * (D / 4) + hl];
        float4 vA = ((const float4*)(g_v + (size_t)sA * D))[hl];
        float dA = dot_bf16(q4, kA);
#pragma unroll
        for (int o = 8; o > 0; o >>= 1)
            dA += __shfl_xor_sync(0xffffffffu, dA, o);
        float exA = __expf(dA);
        acc.x = fmaf(exA, vA.x, acc.x); acc.y = fmaf(exA, vA.y, acc.y);
        acc.z = fmaf(exA, vA.z, acc.z); acc.w = fmaf(exA, vA.w, acc.w);
        s += exA;
    }
    if (i < end) {
        int sA = g_sorted_src[i];
        uint2  kA = kb[(size_t)sA * (D / 4) + hl];
        float4 vA = ((const float4*)(g_v + (size_t)sA * D))[hl];
        float dA = dot_bf16(q4, kA);
#pragma unroll
        for (int o = 8; o > 0; o >>= 1)
            dA += __shfl_xor_sync(0xffffffffu, dA, o);
        float exA = half ? 0.f : __expf(dA);
        acc.x = fmaf(exA, vA.x, acc.x); acc.y = fmaf(exA, vA.y, acc.y);
        acc.z = fmaf(exA, vA.z, acc.z); acc.w = fmaf(exA, vA.w, acc.w);
        s += exA;
    }

    acc.x += __shfl_xor_sync(0xffffffffu, acc.x, 16);
    acc.y += __shfl_xor_sync(0xffffffffu, acc.y, 16);
    acc.z += __shfl_xor_sync(0xffffffffu, acc.z, 16);
    acc.w += __shfl_xor_sync(0xffffffffu, acc.w, 16);
    s     += __shfl_xor_sync(0xffffffffu, s, 16);

    float r = 1.0f / (s + 1e-16f);
    float4 sk = ((const float4*)(g_skip + (size_t)dst * D))[hl];
    float4 o;
    o.x = fmaf(acc.x, r, sk.x);
    o.y = fmaf(acc.y, r, sk.y);
    o.z = fmaf(acc.z, r, sk.z);
    o.w = fmaf(acc.w, r, sk.w);
    if (lane < 16)
        ((float4*)(out + (size_t)dst * D))[hl] = o;
}

// ---------------------------------------------------------------------------
extern "C" void kernel_launch(void* const* d_in, const int* in_sizes, int n_in,
                              void* d_out, int out_size) {
    const float* x  = (const float*)d_in[0];
    const int*   ei = (const int*)d_in[1];   // int64 in ref -> delivered int32
    // d_in[2] = edge_type (unused by reference)
    const float* Wq = (const float*)d_in[3];
    const float* bq = (const float*)d_in[4];
    const float* Wk = (const float*)d_in[5];
    const float* bk = (const float*)d_in[6];
    const float* Wv = (const float*)d_in[7];
    const float* bv = (const float*)d_in[8];
    const float* Ws = (const float*)d_in[9];
    const float* bs = (const float*)d_in[10];
    float* out = (float*)d_out;

    int n = in_sizes[0] / D;   // 100000
    int E = in_sizes[2];       // 1200000
    if (n > NN) n = NN;
    if (E > EE) E = EE;

    float *gq, *gv, *gsk;
    __nv_bfloat16* gkb;
    int* gcnt;
    cudaGetSymbolAddress((void**)&gq,   g_q);
    cudaGetSymbolAddress((void**)&gkb,  g_kbf);
    cudaGetSymbolAddress((void**)&gv,   g_v);
    cudaGetSymbolAddress((void**)&gsk,  g_skip);
    cudaGetSymbolAddress((void**)&gcnt, g_counts);

    int nblk = (n + SCH - 1) / SCH;

    static cudaStream_t s_side = nullptr;
    static cudaEvent_t  ev_fork = nullptr, ev_join = nullptr;
    if (s_side == nullptr) {
        cudaStreamCreateWithFlags(&s_side, cudaStreamNonBlocking);
        cudaEventCreateWithFlags(&ev_fork, cudaEventDisableTiming);
        cudaEventCreateWithFlags(&ev_join, cudaEventDisableTiming);
    }

    // ---- fork: GEMM on side stream, concurrent with CSR build ----
    cudaEventRecord(ev_fork, 0);
    cudaStreamWaitEvent(s_side, ev_fork, 0);
    {
        dim3 grid((n + GR - 1) / GR, 4);
        gemm_one<<<grid, 128, 0, s_side>>>(x, Wq, bq, Wk, bk, Wv, bv, Ws, bs,
                                           gq, gkb, gv, gsk, n);
    }
    cudaEventRecord(ev_join, s_side);

    // ---- CSR build on default stream ----
    cudaMemsetAsync(gcnt, 0, (size_t)n * sizeof(int));
    hist_kernel<<<(E / 4 + 255) / 256, 256>>>(ei, E);
    scan1_kernel<<<nblk, 256>>>(n);
    scan23_kernel<<<nblk, 256>>>(n, nblk);
    scatter_kernel<<<(E / 4 + 255) / 256, 256>>>(ei, E);

    // ---- join, then gather ----
    cudaStreamWaitEvent(0, ev_join, 0);
    {
        int warps_per_block = 8;
        int blocks = (n + warps_per_block - 1) / warps_per_block;
        gather_kernel<<<blocks, 256>>>(out, n);
    }
}

// round 13
// speedup vs baseline: 1.4550x; 1.0847x over previous
#include <cuda_runtime.h>
#include <cuda_fp16.h>

#define NN 100000
#define EE 1200000
#define D  64
#define GR 128     // X rows per GEMM block
#define SCH 1024   // scan chunk (elements per scan block)

// Scratch (device globals: no allocation allowed in kernel_launch)
__device__ float  g_q[(size_t)NN * D];
__device__ __half g_kh[(size_t)NN * D];   // K in fp16 (logits only)
__device__ __half g_vh[(size_t)NN * D];   // V in fp16
__device__ float  g_skip[(size_t)NN * D];
__device__ int    g_counts[NN];
__device__ int    g_offsets[NN];
__device__ int    g_cursor[NN];    // after scatter = segment END
__device__ int    g_partial[128];
__device__ int    g_sorted_src[EE + 16];

// ---------------------------------------------------------------------------
// packed f32x2 helpers (Blackwell sm_100+)
// ---------------------------------------------------------------------------
__device__ __forceinline__ unsigned long long dup_f32x2(float x) {
    unsigned long long r;
    asm("mov.b64 %0, {%1, %1};" : "=l"(r) : "f"(x));
    return r;
}
__device__ __forceinline__ void fma_f32x2(unsigned long long& acc,
                                          unsigned long long a,
                                          unsigned long long b) {
    asm("fma.rn.f32x2 %0, %1, %2, %3;" : "=l"(acc) : "l"(a), "l"(b), "l"(acc));
}
__device__ __forceinline__ float2 unpack_f32x2(unsigned long long p) {
    float lo, hi;
    asm("mov.b64 {%0, %1}, %2;" : "=f"(lo), "=f"(hi) : "l"(p));
    return make_float2(lo, hi);
}

// ---------------------------------------------------------------------------
// K_GEMM: blockIdx.y in {0..3} selects W/b/Y (q,k,v,skip).
// y==1 (K) and y==2 (V) store fp16; q and skip store fp32.
// ---------------------------------------------------------------------------
__global__ void __launch_bounds__(128) gemm_one(
    const float* __restrict__ X,
    const float* __restrict__ Wq, const float* __restrict__ bq,
    const float* __restrict__ Wk, const float* __restrict__ bk,
    const float* __restrict__ Wv, const float* __restrict__ bv,
    const float* __restrict__ Ws, const float* __restrict__ bs,
    float* __restrict__ Yq, __half* __restrict__ Ykh,
    __half* __restrict__ Yvh, float* __restrict__ Ys, int n) {
    __shared__ float xsT[D][GR];   // [k][row]
    __shared__ float ws[D][D];

    int tid  = threadIdx.x;
    int row0 = blockIdx.x * GR;

    const float* W; const float* B;
    switch (blockIdx.y) {
        case 0:  W = Wq; B = bq; break;
        case 1:  W = Wk; B = bk; break;
        case 2:  W = Wv; B = bv; break;
        default: W = Ws; B = bs; break;
    }

    for (int i = tid; i < D * D / 4; i += 128)
        ((float4*)ws)[i] = ((const float4*)W)[i];

    {
        int r = tid;
        bool ok = (row0 + r < n);
#pragma unroll
        for (int c4 = 0; c4 < D / 4; c4++) {
            float4 v = make_float4(0.f, 0.f, 0.f, 0.f);
            if (ok)
                v = ((const float4*)X)[(size_t)(row0 + r) * (D / 4) + c4];
            xsT[c4 * 4 + 0][r] = v.x;
            xsT[c4 * 4 + 1][r] = v.y;
            xsT[c4 * 4 + 2][r] = v.z;
            xsT[c4 * 4 + 3][r] = v.w;
        }
    }
    __syncthreads();

    int tr = (tid >> 3) * 8;  // 0..120
    int tc = (tid & 7) * 8;   // 0..56

    unsigned long long acc[8][4];
#pragma unroll
    for (int r = 0; r < 8; r++)
#pragma unroll
        for (int c = 0; c < 4; c++) acc[r][c] = 0ull;

#pragma unroll 4
    for (int kk = 0; kk < D; kk++) {
        float4 xa = *(const float4*)&xsT[kk][tr];
        float4 xb = *(const float4*)&xsT[kk][tr + 4];
        ulonglong2 wA = *(const ulonglong2*)&ws[kk][tc];
        ulonglong2 wB = *(const ulonglong2*)&ws[kk][tc + 4];
        unsigned long long xd[8];
        xd[0] = dup_f32x2(xa.x); xd[1] = dup_f32x2(xa.y);
        xd[2] = dup_f32x2(xa.z); xd[3] = dup_f32x2(xa.w);
        xd[4] = dup_f32x2(xb.x); xd[5] = dup_f32x2(xb.y);
        xd[6] = dup_f32x2(xb.z); xd[7] = dup_f32x2(xb.w);
#pragma unroll
        for (int r = 0; r < 8; r++) {
            fma_f32x2(acc[r][0], xd[r], wA.x);
            fma_f32x2(acc[r][1], xd[r], wA.y);
            fma_f32x2(acc[r][2], xd[r], wB.x);
            fma_f32x2(acc[r][3], xd[r], wB.y);
        }
    }

    float4 bA = ((const float4*)B)[tc / 4];
    float4 bB = ((const float4*)B)[tc / 4 + 1];
    int y = blockIdx.y;
#pragma unroll
    for (int r = 0; r < 8; r++) {
        int grow = row0 + tr + r;
        if (grow < n) {
            float2 p0 = unpack_f32x2(acc[r][0]);
            float2 p1 = unpack_f32x2(acc[r][1]);
            float2 p2 = unpack_f32x2(acc[r][2]);
            float2 p3 = unpack_f32x2(acc[r][3]);
            float4 o0 = make_float4(p0.x + bA.x, p0.y + bA.y,
                                    p1.x + bA.z, p1.y + bA.w);
            float4 o1 = make_float4(p2.x + bB.x, p2.y + bB.y,
                                    p3.x + bB.z, p3.y + bB.w);
            if (y == 1 || y == 2) {
                __half2 ph[4];
                ph[0] = __floats2half2_rn(o0.x, o0.y);
                ph[1] = __floats2half2_rn(o0.z, o0.w);
                ph[2] = __floats2half2_rn(o1.x, o1.y);
                ph[3] = __floats2half2_rn(o1.z, o1.w);
                __half* Yh = (y == 1) ? Ykh : Yvh;
                *((uint4*)(Yh + (size_t)grow * D + tc)) = *(const uint4*)ph;
            } else {
                float* Y = (y == 0) ? Yq : Ys;
                ((float4*)(Y + (size_t)grow * D + tc))[0] = o0;
                ((float4*)(Y + (size_t)grow * D + tc))[1] = o1;
            }
        }
    }
}

// ---------------------------------------------------------------------------
// CSR build: (memset) -> histogram -> scan1 -> scan23 -> scatter
// ---------------------------------------------------------------------------
__global__ void hist_kernel(const int* __restrict__ ei, int E) {
    const int4* d4 = (const int4*)(ei + E);
    int n4 = E >> 2;
    for (int i = blockIdx.x * blockDim.x + threadIdx.x; i < n4;
         i += gridDim.x * blockDim.x) {
        int4 v = d4[i];
        atomicAdd(&g_counts[v.x], 1);
        atomicAdd(&g_counts[v.y], 1);
        atomicAdd(&g_counts[v.z], 1);
        atomicAdd(&g_counts[v.w], 1);
    }
    int t = blockIdx.x * blockDim.x + threadIdx.x;
    if (t < (E & 3)) atomicAdd(&g_counts[ei[E + (n4 << 2) + t]], 1);
}

__global__ void __launch_bounds__(256) scan1_kernel(int n) {
    __shared__ int sdata[256];
    int t    = threadIdx.x;
    int base = blockIdx.x * SCH + t * 4;

    int v[4];
#pragma unroll
    for (int j = 0; j < 4; j++)
        v[j] = (base + j < n) ? g_counts[base + j] : 0;
    int tsum = v[0] + v[1] + v[2] + v[3];

    sdata[t] = tsum;
    __syncthreads();
    for (int off = 1; off < 256; off <<= 1) {
        int x = (t >= off) ? sdata[t - off] : 0;
        __syncthreads();
        sdata[t] += x;
        __syncthreads();
    }
    int excl = sdata[t] - tsum;
    if (t == 255) g_partial[blockIdx.x] = sdata[255];

    int run = excl;
#pragma unroll
    for (int j = 0; j < 4; j++) {
        if (base + j < n) g_offsets[base + j] = run;
        run += v[j];
    }
}

__global__ void __launch_bounds__(256) scan23_kernel(int n, int nblk) {
    __shared__ int sd[128];
    int t = threadIdx.x;
    if (t < 128) {
        int v = (t < nblk) ? g_partial[t] : 0;
        sd[t] = v;
    }
    __syncthreads();
    for (int off = 1; off < 128; off <<= 1) {
        int x = 0;
        if (t < 128 && t >= off) x = sd[t - off];
        __syncthreads();
        if (t < 128) sd[t] += x;
        __syncthreads();
    }
    int chunk = blockIdx.x;
    int cbase = (chunk > 0) ? sd[chunk - 1] : 0;
    int i0 = chunk * SCH;
    for (int i = i0 + t; i < i0 + SCH && i < n; i += 256)
        g_cursor[i] = g_offsets[i] + cbase;
}

__global__ void scatter_kernel(const int* __restrict__ ei, int E) {
    const int4* s4 = (const int4*)ei;
    const int4* d4 = (const int4*)(ei + E);
    int n4 = E >> 2;
    for (int i = blockIdx.x * blockDim.x + threadIdx.x; i < n4;
         i += gridDim.x * blockDim.x) {
        int4 s = s4[i];
        int4 d = d4[i];
        g_sorted_src[atomicAdd(&g_cursor[d.x], 1)] = s.x;
        g_sorted_src[atomicAdd(&g_cursor[d.y], 1)] = s.y;
        g_sorted_src[atomicAdd(&g_cursor[d.z], 1)] = s.z;
        g_sorted_src[atomicAdd(&g_cursor[d.w], 1)] = s.w;
    }
    int t = blockIdx.x * blockDim.x + threadIdx.x;
    if (t < (E & 3)) {
        int e = (n4 << 2) + t;
        g_sorted_src[atomicAdd(&g_cursor[ei[E + e]], 1)] = ei[e];
    }
}

// ---------------------------------------------------------------------------
// K_GATHER: warp-per-destination, half-warp per edge, 6 edges in flight.
// k and v rows are fp16 (LDG.64/lane each), converted to fp32.
// q is pre-scaled by 1/8 so exp() takes the raw reduced dot.
// ---------------------------------------------------------------------------
__device__ __forceinline__ float dot_f16(float4 q4, uint2 kraw) {
    float2 lo = __half22float2(*(const __half2*)&kraw.x);
    float2 hi = __half22float2(*(const __half2*)&kraw.y);
    return fmaf(q4.x, lo.x, fmaf(q4.y, lo.y, fmaf(q4.z, hi.x, q4.w * hi.y)));
}
__device__ __forceinline__ void acc_f16(float4& acc, float ex, uint2 vraw) {
    float2 lo = __half22float2(*(const __half2*)&vraw.x);
    float2 hi = __half22float2(*(const __half2*)&vraw.y);
    acc.x = fmaf(ex, lo.x, acc.x);
    acc.y = fmaf(ex, lo.y, acc.y);
    acc.z = fmaf(ex, hi.x, acc.z);
    acc.w = fmaf(ex, hi.y, acc.w);
}

__global__ void __launch_bounds__(256) gather_kernel(
    float* __restrict__ out, int n) {
    int warp = (blockIdx.x * blockDim.x + threadIdx.x) >> 5;
    int lane = threadIdx.x & 31;
    if (warp >= n) return;

    int dst  = warp;
    int end  = g_cursor[dst];
    int beg  = end - g_counts[dst];
    int half = lane >> 4;
    int hl   = lane & 15;

    float4 q4 = ((const float4*)(g_q + (size_t)dst * D))[hl];
    q4.x *= 0.125f; q4.y *= 0.125f; q4.z *= 0.125f; q4.w *= 0.125f;

    const uint2* kb = (const uint2*)g_kh;   // 4 fp16 per uint2
    const uint2* vb = (const uint2*)g_vh;

    float4 acc = make_float4(0.f, 0.f, 0.f, 0.f);
    float  s   = 0.f;

    int i = beg;
    for (; i + 5 < end; i += 6) {
        int sA = g_sorted_src[i + half];
        int sB = g_sorted_src[i + 2 + half];
        int sC = g_sorted_src[i + 4 + half];
        uint2 kA = kb[(size_t)sA * (D / 4) + hl];
        uint2 kB = kb[(size_t)sB * (D / 4) + hl];
        uint2 kC = kb[(size_t)sC * (D / 4) + hl];
        uint2 vA = vb[(size_t)sA * (D / 4) + hl];
        uint2 vB = vb[(size_t)sB * (D / 4) + hl];
        uint2 vC = vb[(size_t)sC * (D / 4) + hl];
        float dA = dot_f16(q4, kA);
        float dB = dot_f16(q4, kB);
        float dC = dot_f16(q4, kC);
#pragma unroll
        for (int o = 8; o > 0; o >>= 1) {
            dA += __shfl_xor_sync(0xffffffffu, dA, o);
            dB += __shfl_xor_sync(0xffffffffu, dB, o);
            dC += __shfl_xor_sync(0xffffffffu, dC, o);
        }
        float exA = __expf(dA);
        float exB = __expf(dB);
        float exC = __expf(dC);
        acc_f16(acc, exA, vA);
        acc_f16(acc, exB, vB);
        acc_f16(acc, exC, vC);
        s += exA + exB + exC;
    }
    for (; i + 1 < end; i += 2) {
        int sA = g_sorted_src[i + half];
        uint2 kA = kb[(size_t)sA * (D / 4) + hl];
        uint2 vA = vb[(size_t)sA * (D / 4) + hl];
        float dA = dot_f16(q4, kA);
#pragma unroll
        for (int o = 8; o > 0; o >>= 1)
            dA += __shfl_xor_sync(0xffffffffu, dA, o);
        float exA = __expf(dA);
        acc_f16(acc, exA, vA);
        s += exA;
    }
    if (i < end) {
        int sA = g_sorted_src[i];
        uint2 kA = kb[(size_t)sA * (D / 4) + hl];
        uint2 vA = vb[(size_t)sA * (D / 4) + hl];
        float dA = dot_f16(q4, kA);
#pragma unroll
        for (int o = 8; o > 0; o >>= 1)
            dA += __shfl_xor_sync(0xffffffffu, dA, o);
        float exA = half ? 0.f : __expf(dA);
        acc_f16(acc, exA, vA);
        s += exA;
    }

    acc.x += __shfl_xor_sync(0xffffffffu, acc.x, 16);
    acc.y += __shfl_xor_sync(0xffffffffu, acc.y, 16);
    acc.z += __shfl_xor_sync(0xffffffffu, acc.z, 16);
    acc.w += __shfl_xor_sync(0xffffffffu, acc.w, 16);
    s     += __shfl_xor_sync(0xffffffffu, s, 16);

    float r = 1.0f / (s + 1e-16f);
    float4 sk = ((const float4*)(g_skip + (size_t)dst * D))[hl];
    float4 o;
    o.x = fmaf(acc.x, r, sk.x);
    o.y = fmaf(acc.y, r, sk.y);
    o.z = fmaf(acc.z, r, sk.z);
    o.w = fmaf(acc.w, r, sk.w);
    if (lane < 16)
        ((float4*)(out + (size_t)dst * D))[hl] = o;
}

// ---------------------------------------------------------------------------
extern "C" void kernel_launch(void* const* d_in, const int* in_sizes, int n_in,
                              void* d_out, int out_size) {
    const float* x  = (const float*)d_in[0];
    const int*   ei = (const int*)d_in[1];   // int64 in ref -> delivered int32
    // d_in[2] = edge_type (unused by reference)
    const float* Wq = (const float*)d_in[3];
    const float* bq = (const float*)d_in[4];
    const float* Wk = (const float*)d_in[5];
    const float* bk = (const float*)d_in[6];
    const float* Wv = (const float*)d_in[7];
    const float* bv = (const float*)d_in[8];
    const float* Ws = (const float*)d_in[9];
    const float* bs = (const float*)d_in[10];
    float* out = (float*)d_out;

    int n = in_sizes[0] / D;   // 100000
    int E = in_sizes[2];       // 1200000
    if (n > NN) n = NN;
    if (E > EE) E = EE;

    float *gq, *gsk;
    __half *gkh, *gvh;
    int* gcnt;
    cudaGetSymbolAddress((void**)&gq,   g_q);
    cudaGetSymbolAddress((void**)&gkh,  g_kh);
    cudaGetSymbolAddress((void**)&gvh,  g_vh);
    cudaGetSymbolAddress((void**)&gsk,  g_skip);
    cudaGetSymbolAddress((void**)&gcnt, g_counts);

    int nblk = (n + SCH - 1) / SCH;

    static cudaStream_t s_side = nullptr;
    static cudaEvent_t  ev_fork = nullptr, ev_join = nullptr;
    if (s_side == nullptr) {
        cudaStreamCreateWithFlags(&s_side, cudaStreamNonBlocking);
        cudaEventCreateWithFlags(&ev_fork, cudaEventDisableTiming);
        cudaEventCreateWithFlags(&ev_join, cudaEventDisableTiming);
    }

    // ---- fork: GEMM on side stream, concurrent with CSR build ----
    cudaEventRecord(ev_fork, 0);
    cudaStreamWaitEvent(s_side, ev_fork, 0);
    {
        dim3 grid((n + GR - 1) / GR, 4);
        gemm_one<<<grid, 128, 0, s_side>>>(x, Wq, bq, Wk, bk, Wv, bv, Ws, bs,
                                           gq, gkh, gvh, gsk, n);
    }
    cudaEventRecord(ev_join, s_side);

    // ---- CSR build on default stream ----
    cudaMemsetAsync(gcnt, 0, (size_t)n * sizeof(int));
    hist_kernel<<<(E / 4 + 255) / 256, 256>>>(ei, E);
    scan1_kernel<<<nblk, 256>>>(n);
    scan23_kernel<<<nblk, 256>>>(n, nblk);
    scatter_kernel<<<(E / 4 + 255) / 256, 256>>>(ei, E);

    // ---- join, then gather ----
    cudaStreamWaitEvent(0, ev_join, 0);
    {
        int warps_per_block = 8;
        int blocks = (n + warps_per_block - 1) / warps_per_block;
        gather_kernel<<<blocks, 256>>>(out, n);
    }
}

// round 14
// speedup vs baseline: 1.4698x; 1.0102x over previous
#include <cuda_runtime.h>
#include <cuda_fp16.h>

#define NN 100000
#define EE 1200000
#define D  64
#define GR 128     // X rows per GEMM block
#define SCH 1024   // scan chunk (elements per scan block)

// Scratch (device globals: no allocation allowed in kernel_launch).
// g_counts and g_flag are zero at load; the tail kernel re-zeroes them at the
// end of every launch so hist/scan can rely on zeroed state without a memset.
__device__ float  g_q[(size_t)NN * D];
__device__ __half g_kh[(size_t)NN * D];   // K in fp16 (logits only)
__device__ __half g_vh[(size_t)NN * D];   // V in fp16
__device__ float  g_skip[(size_t)NN * D];
__device__ int    g_counts[NN];
__device__ int    g_cursor[NN];    // scan output; after scatter = segment END
__device__ int    g_agg[128];      // per-chunk aggregates (lookback scan)
__device__ int    g_flag[128];     // publish flags
__device__ int    g_sorted_src[EE + 16];

// ---------------------------------------------------------------------------
// packed f32x2 helpers (Blackwell sm_100+)
// ---------------------------------------------------------------------------
__device__ __forceinline__ unsigned long long dup_f32x2(float x) {
    unsigned long long r;
    asm("mov.b64 %0, {%1, %1};" : "=l"(r) : "f"(x));
    return r;
}
__device__ __forceinline__ void fma_f32x2(unsigned long long& acc,
                                          unsigned long long a,
                                          unsigned long long b) {
    asm("fma.rn.f32x2 %0, %1, %2, %3;" : "=l"(acc) : "l"(a), "l"(b), "l"(acc));
}
__device__ __forceinline__ float2 unpack_f32x2(unsigned long long p) {
    float lo, hi;
    asm("mov.b64 {%0, %1}, %2;" : "=f"(lo), "=f"(hi) : "l"(p));
    return make_float2(lo, hi);
}

// ---------------------------------------------------------------------------
// K_GEMM: blockIdx.y in {0..3} selects W/b/Y (q,k,v,skip).
// y==1 (K) and y==2 (V) store fp16; q and skip store fp32.
// ---------------------------------------------------------------------------
__global__ void __launch_bounds__(128) gemm_one(
    const float* __restrict__ X,
    const float* __restrict__ Wq, const float* __restrict__ bq,
    const float* __restrict__ Wk, const float* __restrict__ bk,
    const float* __restrict__ Wv, const float* __restrict__ bv,
    const float* __restrict__ Ws, const float* __restrict__ bs,
    float* __restrict__ Yq, __half* __restrict__ Ykh,
    __half* __restrict__ Yvh, float* __restrict__ Ys, int n) {
    __shared__ float xsT[D][GR];   // [k][row]
    __shared__ float ws[D][D];

    int tid  = threadIdx.x;
    int row0 = blockIdx.x * GR;

    const float* W; const float* B;
    switch (blockIdx.y) {
        case 0:  W = Wq; B = bq; break;
        case 1:  W = Wk; B = bk; break;
        case 2:  W = Wv; B = bv; break;
        default: W = Ws; B = bs; break;
    }

    for (int i = tid; i < D * D / 4; i += 128)
        ((float4*)ws)[i] = ((const float4*)W)[i];

    {
        int r = tid;
        bool ok = (row0 + r < n);
#pragma unroll
        for (int c4 = 0; c4 < D / 4; c4++) {
            float4 v = make_float4(0.f, 0.f, 0.f, 0.f);
            if (ok)
                v = ((const float4*)X)[(size_t)(row0 + r) * (D / 4) + c4];
            xsT[c4 * 4 + 0][r] = v.x;
            xsT[c4 * 4 + 1][r] = v.y;
            xsT[c4 * 4 + 2][r] = v.z;
            xsT[c4 * 4 + 3][r] = v.w;
        }
    }
    __syncthreads();

    int tr = (tid >> 3) * 8;  // 0..120
    int tc = (tid & 7) * 8;   // 0..56

    unsigned long long acc[8][4];
#pragma unroll
    for (int r = 0; r < 8; r++)
#pragma unroll
        for (int c = 0; c < 4; c++) acc[r][c] = 0ull;

#pragma unroll 4
    for (int kk = 0; kk < D; kk++) {
        float4 xa = *(const float4*)&xsT[kk][tr];
        float4 xb = *(const float4*)&xsT[kk][tr + 4];
        ulonglong2 wA = *(const ulonglong2*)&ws[kk][tc];
        ulonglong2 wB = *(const ulonglong2*)&ws[kk][tc + 4];
        unsigned long long xd[8];
        xd[0] = dup_f32x2(xa.x); xd[1] = dup_f32x2(xa.y);
        xd[2] = dup_f32x2(xa.z); xd[3] = dup_f32x2(xa.w);
        xd[4] = dup_f32x2(xb.x); xd[5] = dup_f32x2(xb.y);
        xd[6] = dup_f32x2(xb.z); xd[7] = dup_f32x2(xb.w);
#pragma unroll
        for (int r = 0; r < 8; r++) {
            fma_f32x2(acc[r][0], xd[r], wA.x);
            fma_f32x2(acc[r][1], xd[r], wA.y);
            fma_f32x2(acc[r][2], xd[r], wB.x);
            fma_f32x2(acc[r][3], xd[r], wB.y);
        }
    }

    float4 bA = ((const float4*)B)[tc / 4];
    float4 bB = ((const float4*)B)[tc / 4 + 1];
    int y = blockIdx.y;
#pragma unroll
    for (int r = 0; r < 8; r++) {
        int grow = row0 + tr + r;
        if (grow < n) {
            float2 p0 = unpack_f32x2(acc[r][0]);
            float2 p1 = unpack_f32x2(acc[r][1]);
            float2 p2 = unpack_f32x2(acc[r][2]);
            float2 p3 = unpack_f32x2(acc[r][3]);
            float4 o0 = make_float4(p0.x + bA.x, p0.y + bA.y,
                                    p1.x + bA.z, p1.y + bA.w);
            float4 o1 = make_float4(p2.x + bB.x, p2.y + bB.y,
                                    p3.x + bB.z, p3.y + bB.w);
            if (y == 1 || y == 2) {
                __half2 ph[4];
                ph[0] = __floats2half2_rn(o0.x, o0.y);
                ph[1] = __floats2half2_rn(o0.z, o0.w);
                ph[2] = __floats2half2_rn(o1.x, o1.y);
                ph[3] = __floats2half2_rn(o1.z, o1.w);
                __half* Yh = (y == 1) ? Ykh : Yvh;
                *((uint4*)(Yh + (size_t)grow * D + tc)) = *(const uint4*)ph;
            } else {
                float* Y = (y == 0) ? Yq : Ys;
                ((float4*)(Y + (size_t)grow * D + tc))[0] = o0;
                ((float4*)(Y + (size_t)grow * D + tc))[1] = o1;
            }
        }
    }
}

// ---------------------------------------------------------------------------
// CSR build: histogram -> fused decoupled-lookback scan -> scatter
// (g_counts/g_flag arrive zeroed: static zero-init on first call, tail_zero
//  kernel at the end of every launch thereafter.)
// ---------------------------------------------------------------------------
__global__ void hist_kernel(const int* __restrict__ ei, int E) {
    const int4* d4 = (const int4*)(ei + E);
    int n4 = E >> 2;
    for (int i = blockIdx.x * blockDim.x + threadIdx.x; i < n4;
         i += gridDim.x * blockDim.x) {
        int4 v = d4[i];
        atomicAdd(&g_counts[v.x], 1);
        atomicAdd(&g_counts[v.y], 1);
        atomicAdd(&g_counts[v.z], 1);
        atomicAdd(&g_counts[v.w], 1);
    }
    int t = blockIdx.x * blockDim.x + threadIdx.x;
    if (t < (E & 3)) atomicAdd(&g_counts[ei[E + (n4 << 2) + t]], 1);
}

// single-kernel exclusive scan over g_counts -> g_cursor.
// 98 blocks, all co-resident; each publishes its chunk aggregate with a
// release flag, then sums all predecessors' aggregates (parallel lookback).
__global__ void __launch_bounds__(256) scan_fused(int n, int nblk) {
    __shared__ int sdata[256];
    int b    = blockIdx.x;
    int t    = threadIdx.x;
    int base = b * SCH + t * 4;

    int v[4];
#pragma unroll
    for (int j = 0; j < 4; j++)
        v[j] = (base + j < n) ? g_counts[base + j] : 0;
    int tsum = v[0] + v[1] + v[2] + v[3];

    // block-wide inclusive scan of per-thread sums
    sdata[t] = tsum;
    __syncthreads();
    for (int off = 1; off < 256; off <<= 1) {
        int x = (t >= off) ? sdata[t - off] : 0;
        __syncthreads();
        sdata[t] += x;
        __syncthreads();
    }
    int excl  = sdata[t] - tsum;   // exclusive within chunk
    int total = sdata[255];        // chunk aggregate (valid: loop ends in sync)

    // publish aggregate with release
    if (t == 0) {
        g_agg[b] = total;
        __threadfence();
        atomicExch(&g_flag[b], 1);
    }

    // lookback: thread t (t < b) acquires predecessor t's aggregate
    int mine = 0;
    if (t < b) {
        while (atomicAdd(&g_flag[t], 0) == 0) {}
        __threadfence();
        mine = g_agg[t];
    }
    __syncthreads();           // sdata free for reuse
    sdata[t] = mine;
    __syncthreads();
    for (int off = 128; off > 0; off >>= 1) {
        if (t < off) sdata[t] += sdata[t + off];
        __syncthreads();
    }
    int cbase = sdata[0];      // sum of predecessor aggregates

    int run = excl + cbase;
#pragma unroll
    for (int j = 0; j < 4; j++) {
        if (base + j < n) g_cursor[base + j] = run;
        run += v[j];
    }
}

__global__ void scatter_kernel(const int* __restrict__ ei, int E) {
    const int4* s4 = (const int4*)ei;
    const int4* d4 = (const int4*)(ei + E);
    int n4 = E >> 2;
    for (int i = blockIdx.x * blockDim.x + threadIdx.x; i < n4;
         i += gridDim.x * blockDim.x) {
        int4 s = s4[i];
        int4 d = d4[i];
        g_sorted_src[atomicAdd(&g_cursor[d.x], 1)] = s.x;
        g_sorted_src[atomicAdd(&g_cursor[d.y], 1)] = s.y;
        g_sorted_src[atomicAdd(&g_cursor[d.z], 1)] = s.z;
        g_sorted_src[atomicAdd(&g_cursor[d.w], 1)] = s.w;
    }
    int t = blockIdx.x * blockDim.x + threadIdx.x;
    if (t < (E & 3)) {
        int e = (n4 << 2) + t;
        g_sorted_src[atomicAdd(&g_cursor[ei[E + e]], 1)] = ei[e];
    }
}

// tail: restore zeroed state for the next replay (runs after gather)
__global__ void tail_zero(int n) {
    int i = blockIdx.x * blockDim.x + threadIdx.x;
    if (i < n)   g_counts[i] = 0;
    if (i < 128) g_flag[i] = 0;
}

// ---------------------------------------------------------------------------
// K_GATHER: warp-per-destination, half-warp per edge, 6 edges in flight.
// k and v rows are fp16 (LDG.64/lane each), converted to fp32.
// q is pre-scaled by 1/8 so exp() takes the raw reduced dot.
// ---------------------------------------------------------------------------
__device__ __forceinline__ float dot_f16(float4 q4, uint2 kraw) {
    float2 lo = __half22float2(*(const __half2*)&kraw.x);
    float2 hi = __half22float2(*(const __half2*)&kraw.y);
    return fmaf(q4.x, lo.x, fmaf(q4.y, lo.y, fmaf(q4.z, hi.x, q4.w * hi.y)));
}
__device__ __forceinline__ void acc_f16(float4& acc, float ex, uint2 vraw) {
    float2 lo = __half22float2(*(const __half2*)&vraw.x);
    float2 hi = __half22float2(*(const __half2*)&vraw.y);
    acc.x = fmaf(ex, lo.x, acc.x);
    acc.y = fmaf(ex, lo.y, acc.y);
    acc.z = fmaf(ex, hi.x, acc.z);
    acc.w = fmaf(ex, hi.y, acc.w);
}

__global__ void __launch_bounds__(256) gather_kernel(
    float* __restrict__ out, int n) {
    int warp = (blockIdx.x * blockDim.x + threadIdx.x) >> 5;
    int lane = threadIdx.x & 31;
    if (warp >= n) return;

    int dst  = warp;
    int end  = g_cursor[dst];
    int beg  = end - g_counts[dst];
    int half = lane >> 4;
    int hl   = lane & 15;

    float4 q4 = ((const float4*)(g_q + (size_t)dst * D))[hl];
    q4.x *= 0.125f; q4.y *= 0.125f; q4.z *= 0.125f; q4.w *= 0.125f;

    const uint2* kb = (const uint2*)g_kh;   // 4 fp16 per uint2
    const uint2* vb = (const uint2*)g_vh;

    float4 acc = make_float4(0.f, 0.f, 0.f, 0.f);
    float  s   = 0.f;

    int i = beg;
    for (; i + 5 < end; i += 6) {
        int sA = g_sorted_src[i + half];
        int sB = g_sorted_src[i + 2 + half];
        int sC = g_sorted_src[i + 4 + half];
        uint2 kA = kb[(size_t)sA * (D / 4) + hl];
        uint2 kB = kb[(size_t)sB * (D / 4) + hl];
        uint2 kC = kb[(size_t)sC * (D / 4) + hl];
        uint2 vA = vb[(size_t)sA * (D / 4) + hl];
        uint2 vB = vb[(size_t)sB * (D / 4) + hl];
        uint2 vC = vb[(size_t)sC * (D / 4) + hl];
        float dA = dot_f16(q4, kA);
        float dB = dot_f16(q4, kB);
        float dC = dot_f16(q4, kC);
#pragma unroll
        for (int o = 8; o > 0; o >>= 1) {
            dA += __shfl_xor_sync(0xffffffffu, dA, o);
            dB += __shfl_xor_sync(0xffffffffu, dB, o);
            dC += __shfl_xor_sync(0xffffffffu, dC, o);
        }
        float exA = __expf(dA);
        float exB = __expf(dB);
        float exC = __expf(dC);
        acc_f16(acc, exA, vA);
        acc_f16(acc, exB, vB);
        acc_f16(acc, exC, vC);
        s += exA + exB + exC;
    }
    for (; i + 1 < end; i += 2) {
        int sA = g_sorted_src[i + half];
        uint2 kA = kb[(size_t)sA * (D / 4) + hl];
        uint2 vA = vb[(size_t)sA * (D / 4) + hl];
        float dA = dot_f16(q4, kA);
#pragma unroll
        for (int o = 8; o > 0; o >>= 1)
            dA += __shfl_xor_sync(0xffffffffu, dA, o);
        float exA = __expf(dA);
        acc_f16(acc, exA, vA);
        s += exA;
    }
    if (i < end) {
        int sA = g_sorted_src[i];
        uint2 kA = kb[(size_t)sA * (D / 4) + hl];
        uint2 vA = vb[(size_t)sA * (D / 4) + hl];
        float dA = dot_f16(q4, kA);
#pragma unroll
        for (int o = 8; o > 0; o >>= 1)
            dA += __shfl_xor_sync(0xffffffffu, dA, o);
        float exA = half ? 0.f : __expf(dA);
        acc_f16(acc, exA, vA);
        s += exA;
    }

    acc.x += __shfl_xor_sync(0xffffffffu, acc.x, 16);
    acc.y += __shfl_xor_sync(0xffffffffu, acc.y, 16);
    acc.z += __shfl_xor_sync(0xffffffffu, acc.z, 16);
    acc.w += __shfl_xor_sync(0xffffffffu, acc.w, 16);
    s     += __shfl_xor_sync(0xffffffffu, s, 16);

    float r = 1.0f / (s + 1e-16f);
    float4 sk = ((const float4*)(g_skip + (size_t)dst * D))[hl];
    float4 o;
    o.x = fmaf(acc.x, r, sk.x);
    o.y = fmaf(acc.y, r, sk.y);
    o.z = fmaf(acc.z, r, sk.z);
    o.w = fmaf(acc.w, r, sk.w);
    if (lane < 16)
        ((float4*)(out + (size_t)dst * D))[hl] = o;
}

// ---------------------------------------------------------------------------
extern "C" void kernel_launch(void* const* d_in, const int* in_sizes, int n_in,
                              void* d_out, int out_size) {
    const float* x  = (const float*)d_in[0];
    const int*   ei = (const int*)d_in[1];   // int64 in ref -> delivered int32
    // d_in[2] = edge_type (unused by reference)
    const float* Wq = (const float*)d_in[3];
    const float* bq = (const float*)d_in[4];
    const float* Wk = (const float*)d_in[5];
    const float* bk = (const float*)d_in[6];
    const float* Wv = (const float*)d_in[7];
    const float* bv = (const float*)d_in[8];
    const float* Ws = (const float*)d_in[9];
    const float* bs = (const float*)d_in[10];
    float* out = (float*)d_out;

    int n = in_sizes[0] / D;   // 100000
    int E = in_sizes[2];       // 1200000
    if (n > NN) n = NN;
    if (E > EE) E = EE;

    float *gq, *gsk;
    __half *gkh, *gvh;
    cudaGetSymbolAddress((void**)&gq,  g_q);
    cudaGetSymbolAddress((void**)&gkh, g_kh);
    cudaGetSymbolAddress((void**)&gvh, g_vh);
    cudaGetSymbolAddress((void**)&gsk, g_skip);

    int nblk = (n + SCH - 1) / SCH;

    static cudaStream_t s_side = nullptr;
    static cudaEvent_t  ev_fork = nullptr, ev_join = nullptr;
    if (s_side == nullptr) {
        cudaStreamCreateWithFlags(&s_side, cudaStreamNonBlocking);
        cudaEventCreateWithFlags(&ev_fork, cudaEventDisableTiming);
        cudaEventCreateWithFlags(&ev_join, cudaEventDisableTiming);
    }

    // ---- item 1: GEMM on side stream, concurrent with CSR build ----
    cudaEventRecord(ev_fork, 0);
    cudaStreamWaitEvent(s_side, ev_fork, 0);
    {
        dim3 grid((n + GR - 1) / GR, 4);
        gemm_one<<<grid, 128, 0, s_side>>>(x, Wq, bq, Wk, bk, Wv, bv, Ws, bs,
                                           gq, gkh, gvh, gsk, n);
    }
    cudaEventRecord(ev_join, s_side);

    // ---- items 2-4: CSR build on default stream (counts pre-zeroed) ----
    hist_kernel<<<(E / 4 + 255) / 256, 256>>>(ei, E);
    scan_fused<<<nblk, 256>>>(n, nblk);
    scatter_kernel<<<(E / 4 + 255) / 256, 256>>>(ei, E);

    // ---- item 5: gather (after join) ----
    cudaStreamWaitEvent(0, ev_join, 0);
    {
        int warps_per_block = 8;
        int blocks = (n + warps_per_block - 1) / warps_per_block;
        gather_kernel<<<blocks, 256>>>(out, n);
    }

    // ---- item 6: restore zeroed scratch for next replay ----
    tail_zero<<<(n + 255) / 256, 256>>>(n);
}

// round 15
// speedup vs baseline: 1.4718x; 1.0014x over previous
#include <cuda_runtime.h>
#include <cuda_fp16.h>

#define NN 100000
#define EE 1200000
#define D  64
#define GR 128     // X rows per GEMM block
#define SCH 1024   // scan chunk (elements per scan block)

// Scratch (device globals: no allocation allowed in kernel_launch).
// g_counts and g_flag are zero at load; the tail kernel re-zeroes them at the
// end of every launch so hist/scan can rely on zeroed state without a memset.
__device__ float  g_q[(size_t)NN * D];
__device__ __half g_kh[(size_t)NN * D];   // K in fp16 (logits only)
__device__ __half g_vh[(size_t)NN * D];   // V in fp16
__device__ float  g_skip[(size_t)NN * D];
__device__ int    g_counts[NN];
__device__ int    g_cursor[NN];    // scan output; after scatter = segment END
__device__ int    g_agg[128];      // per-chunk aggregates (lookback scan)
__device__ int    g_flag[128];     // publish flags
__device__ int    g_sorted_src[EE + 16];

// ---------------------------------------------------------------------------
// packed f32x2 helpers (Blackwell sm_100+)
// ---------------------------------------------------------------------------
__device__ __forceinline__ unsigned long long dup_f32x2(float x) {
    unsigned long long r;
    asm("mov.b64 %0, {%1, %1};" : "=l"(r) : "f"(x));
    return r;
}
__device__ __forceinline__ void fma_f32x2(unsigned long long& acc,
                                          unsigned long long a,
                                          unsigned long long b) {
    asm("fma.rn.f32x2 %0, %1, %2, %3;" : "=l"(acc) : "l"(a), "l"(b), "l"(acc));
}
__device__ __forceinline__ float2 unpack_f32x2(unsigned long long p) {
    float lo, hi;
    asm("mov.b64 {%0, %1}, %2;" : "=f"(lo), "=f"(hi) : "l"(p));
    return make_float2(lo, hi);
}

// ---------------------------------------------------------------------------
// K_GEMM: blockIdx.y in {0..3} selects W/b/Y (q,k,v,skip).
// y==1 (K) and y==2 (V) store fp16; q and skip store fp32.
// ---------------------------------------------------------------------------
__global__ void __launch_bounds__(128) gemm_one(
    const float* __restrict__ X,
    const float* __restrict__ Wq, const float* __restrict__ bq,
    const float* __restrict__ Wk, const float* __restrict__ bk,
    const float* __restrict__ Wv, const float* __restrict__ bv,
    const float* __restrict__ Ws, const float* __restrict__ bs,
    float* __restrict__ Yq, __half* __restrict__ Ykh,
    __half* __restrict__ Yvh, float* __restrict__ Ys, int n) {
    __shared__ float xsT[D][GR];   // [k][row]
    __shared__ float ws[D][D];

    int tid  = threadIdx.x;
    int row0 = blockIdx.x * GR;

    const float* W; const float* B;
    switch (blockIdx.y) {
        case 0:  W = Wq; B = bq; break;
        case 1:  W = Wk; B = bk; break;
        case 2:  W = Wv; B = bv; break;
        default: W = Ws; B = bs; break;
    }

    for (int i = tid; i < D * D / 4; i += 128)
        ((float4*)ws)[i] = ((const float4*)W)[i];

    {
        int r = tid;
        bool ok = (row0 + r < n);
#pragma unroll
        for (int c4 = 0; c4 < D / 4; c4++) {
            float4 v = make_float4(0.f, 0.f, 0.f, 0.f);
            if (ok)
                v = ((const float4*)X)[(size_t)(row0 + r) * (D / 4) + c4];
            xsT[c4 * 4 + 0][r] = v.x;
            xsT[c4 * 4 + 1][r] = v.y;
            xsT[c4 * 4 + 2][r] = v.z;
            xsT[c4 * 4 + 3][r] = v.w;
        }
    }
    __syncthreads();

    int tr = (tid >> 3) * 8;  // 0..120
    int tc = (tid & 7) * 8;   // 0..56

    unsigned long long acc[8][4];
#pragma unroll
    for (int r = 0; r < 8; r++)
#pragma unroll
        for (int c = 0; c < 4; c++) acc[r][c] = 0ull;

#pragma unroll 4
    for (int kk = 0; kk < D; kk++) {
        float4 xa = *(const float4*)&xsT[kk][tr];
        float4 xb = *(const float4*)&xsT[kk][tr + 4];
        ulonglong2 wA = *(const ulonglong2*)&ws[kk][tc];
        ulonglong2 wB = *(const ulonglong2*)&ws[kk][tc + 4];
        unsigned long long xd[8];
        xd[0] = dup_f32x2(xa.x); xd[1] = dup_f32x2(xa.y);
        xd[2] = dup_f32x2(xa.z); xd[3] = dup_f32x2(xa.w);
        xd[4] = dup_f32x2(xb.x); xd[5] = dup_f32x2(xb.y);
        xd[6] = dup_f32x2(xb.z); xd[7] = dup_f32x2(xb.w);
#pragma unroll
        for (int r = 0; r < 8; r++) {
            fma_f32x2(acc[r][0], xd[r], wA.x);
            fma_f32x2(acc[r][1], xd[r], wA.y);
            fma_f32x2(acc[r][2], xd[r], wB.x);
            fma_f32x2(acc[r][3], xd[r], wB.y);
        }
    }

    float4 bA = ((const float4*)B)[tc / 4];
    float4 bB = ((const float4*)B)[tc / 4 + 1];
    int y = blockIdx.y;
#pragma unroll
    for (int r = 0; r < 8; r++) {
        int grow = row0 + tr + r;
        if (grow < n) {
            float2 p0 = unpack_f32x2(acc[r][0]);
            float2 p1 = unpack_f32x2(acc[r][1]);
            float2 p2 = unpack_f32x2(acc[r][2]);
            float2 p3 = unpack_f32x2(acc[r][3]);
            float4 o0 = make_float4(p0.x + bA.x, p0.y + bA.y,
                                    p1.x + bA.z, p1.y + bA.w);
            float4 o1 = make_float4(p2.x + bB.x, p2.y + bB.y,
                                    p3.x + bB.z, p3.y + bB.w);
            if (y == 1 || y == 2) {
                __half2 ph[4];
                ph[0] = __floats2half2_rn(o0.x, o0.y);
                ph[1] = __floats2half2_rn(o0.z, o0.w);
                ph[2] = __floats2half2_rn(o1.x, o1.y);
                ph[3] = __floats2half2_rn(o1.z, o1.w);
                __half* Yh = (y == 1) ? Ykh : Yvh;
                *((uint4*)(Yh + (size_t)grow * D + tc)) = *(const uint4*)ph;
            } else {
                float* Y = (y == 0) ? Yq : Ys;
                ((float4*)(Y + (size_t)grow * D + tc))[0] = o0;
                ((float4*)(Y + (size_t)grow * D + tc))[1] = o1;
            }
        }
    }
}

// ---------------------------------------------------------------------------
// CSR build: histogram -> fused decoupled-lookback scan -> scatter
// (g_counts/g_flag arrive zeroed: static zero-init on first call, tail_zero
//  kernel at the end of every launch thereafter.)
// ---------------------------------------------------------------------------
__global__ void hist_kernel(const int* __restrict__ ei, int E) {
    const int4* d4 = (const int4*)(ei + E);
    int n4 = E >> 2;
    for (int i = blockIdx.x * blockDim.x + threadIdx.x; i < n4;
         i += gridDim.x * blockDim.x) {
        int4 v = d4[i];
        atomicAdd(&g_counts[v.x], 1);
        atomicAdd(&g_counts[v.y], 1);
        atomicAdd(&g_counts[v.z], 1);
        atomicAdd(&g_counts[v.w], 1);
    }
    int t = blockIdx.x * blockDim.x + threadIdx.x;
    if (t < (E & 3)) atomicAdd(&g_counts[ei[E + (n4 << 2) + t]], 1);
}

// single-kernel exclusive scan over g_counts -> g_cursor.
// 98 blocks, all co-resident; each publishes its chunk aggregate with a
// release flag, then sums all predecessors' aggregates (parallel lookback).
__global__ void __launch_bounds__(256) scan_fused(int n, int nblk) {
    __shared__ int sdata[256];
    int b    = blockIdx.x;
    int t    = threadIdx.x;
    int base = b * SCH + t * 4;

    int v[4];
#pragma unroll
    for (int j = 0; j < 4; j++)
        v[j] = (base + j < n) ? g_counts[base + j] : 0;
    int tsum = v[0] + v[1] + v[2] + v[3];

    // block-wide inclusive scan of per-thread sums
    sdata[t] = tsum;
    __syncthreads();
    for (int off = 1; off < 256; off <<= 1) {
        int x = (t >= off) ? sdata[t - off] : 0;
        __syncthreads();
        sdata[t] += x;
        __syncthreads();
    }
    int excl  = sdata[t] - tsum;   // exclusive within chunk
    int total = sdata[255];        // chunk aggregate (valid: loop ends in sync)

    // publish aggregate with release
    if (t == 0) {
        g_agg[b] = total;
        __threadfence();
        atomicExch(&g_flag[b], 1);
    }

    // lookback: thread t (t < b) acquires predecessor t's aggregate
    int mine = 0;
    if (t < b) {
        while (atomicAdd(&g_flag[t], 0) == 0) {}
        __threadfence();
        mine = g_agg[t];
    }
    __syncthreads();           // sdata free for reuse
    sdata[t] = mine;
    __syncthreads();
    for (int off = 128; off > 0; off >>= 1) {
        if (t < off) sdata[t] += sdata[t + off];
        __syncthreads();
    }
    int cbase = sdata[0];      // sum of predecessor aggregates

    int run = excl + cbase;
#pragma unroll
    for (int j = 0; j < 4; j++) {
        if (base + j < n) g_cursor[base + j] = run;
        run += v[j];
    }
}

__global__ void scatter_kernel(const int* __restrict__ ei, int E) {
    const int4* s4 = (const int4*)ei;
    const int4* d4 = (const int4*)(ei + E);
    int n4 = E >> 2;
    for (int i = blockIdx.x * blockDim.x + threadIdx.x; i < n4;
         i += gridDim.x * blockDim.x) {
        int4 s = s4[i];
        int4 d = d4[i];
        g_sorted_src[atomicAdd(&g_cursor[d.x], 1)] = s.x;
        g_sorted_src[atomicAdd(&g_cursor[d.y], 1)] = s.y;
        g_sorted_src[atomicAdd(&g_cursor[d.z], 1)] = s.z;
        g_sorted_src[atomicAdd(&g_cursor[d.w], 1)] = s.w;
    }
    int t = blockIdx.x * blockDim.x + threadIdx.x;
    if (t < (E & 3)) {
        int e = (n4 << 2) + t;
        g_sorted_src[atomicAdd(&g_cursor[ei[E + e]], 1)] = ei[e];
    }
}

// tail: restore zeroed state for the next replay (runs after gather)
__global__ void tail_zero(int n) {
    int i = blockIdx.x * blockDim.x + threadIdx.x;
    if (i < n)   g_counts[i] = 0;
    if (i < 128) g_flag[i] = 0;
}

// ---------------------------------------------------------------------------
// K_GATHER: warp-per-destination, half-warp per edge, 6 edges in flight.
// k and v rows are fp16 (LDG.64/lane each), converted to fp32.
// q is pre-scaled by 1/8 so exp() takes the raw reduced dot.
// ---------------------------------------------------------------------------
__device__ __forceinline__ float dot_f16(float4 q4, uint2 kraw) {
    float2 lo = __half22float2(*(const __half2*)&kraw.x);
    float2 hi = __half22float2(*(const __half2*)&kraw.y);
    return fmaf(q4.x, lo.x, fmaf(q4.y, lo.y, fmaf(q4.z, hi.x, q4.w * hi.y)));
}
__device__ __forceinline__ void acc_f16(float4& acc, float ex, uint2 vraw) {
    float2 lo = __half22float2(*(const __half2*)&vraw.x);
    float2 hi = __half22float2(*(const __half2*)&vraw.y);
    acc.x = fmaf(ex, lo.x, acc.x);
    acc.y = fmaf(ex, lo.y, acc.y);
    acc.z = fmaf(ex, hi.x, acc.z);
    acc.w = fmaf(ex, hi.y, acc.w);
}

__global__ void __launch_bounds__(256) gather_kernel(
    float* __restrict__ out, int n) {
    int warp = (blockIdx.x * blockDim.x + threadIdx.x) >> 5;
    int lane = threadIdx.x & 31;
    if (warp >= n) return;

    int dst  = warp;
    int end  = g_cursor[dst];
    int beg  = end - g_counts[dst];
    int half = lane >> 4;
    int hl   = lane & 15;

    float4 q4 = ((const float4*)(g_q + (size_t)dst * D))[hl];
    q4.x *= 0.125f; q4.y *= 0.125f; q4.z *= 0.125f; q4.w *= 0.125f;

    const uint2* kb = (const uint2*)g_kh;   // 4 fp16 per uint2
    const uint2* vb = (const uint2*)g_vh;

    float4 acc = make_float4(0.f, 0.f, 0.f, 0.f);
    float  s   = 0.f;

    int i = beg;
    for (; i + 5 < end; i += 6) {
        int sA = g_sorted_src[i + half];
        int sB = g_sorted_src[i + 2 + half];
        int sC = g_sorted_src[i + 4 + half];
        uint2 kA = kb[(size_t)sA * (D / 4) + hl];
        uint2 kB = kb[(size_t)sB * (D / 4) + hl];
        uint2 kC = kb[(size_t)sC * (D / 4) + hl];
        uint2 vA = vb[(size_t)sA * (D / 4) + hl];
        uint2 vB = vb[(size_t)sB * (D / 4) + hl];
        uint2 vC = vb[(size_t)sC * (D / 4) + hl];
        float dA = dot_f16(q4, kA);
        float dB = dot_f16(q4, kB);
        float dC = dot_f16(q4, kC);
#pragma unroll
        for (int o = 8; o > 0; o >>= 1) {
            dA += __shfl_xor_sync(0xffffffffu, dA, o);
            dB += __shfl_xor_sync(0xffffffffu, dB, o);
            dC += __shfl_xor_sync(0xffffffffu, dC, o);
        }
        float exA = __expf(dA);
        float exB = __expf(dB);
        float exC = __expf(dC);
        acc_f16(acc, exA, vA);
        acc_f16(acc, exB, vB);
        acc_f16(acc, exC, vC);
        s += exA + exB + exC;
    }
    for (; i + 1 < end; i += 2) {
        int sA = g_sorted_src[i + half];
        uint2 kA = kb[(size_t)sA * (D / 4) + hl];
        uint2 vA = vb[(size_t)sA * (D / 4) + hl];
        float dA = dot_f16(q4, kA);
#pragma unroll
        for (int o = 8; o > 0; o >>= 1)
            dA += __shfl_xor_sync(0xffffffffu, dA, o);
        float exA = __expf(dA);
        acc_f16(acc, exA, vA);
        s += exA;
    }
    if (i < end) {
        int sA = g_sorted_src[i];
        uint2 kA = kb[(size_t)sA * (D / 4) + hl];
        uint2 vA = vb[(size_t)sA * (D / 4) + hl];
        float dA = dot_f16(q4, kA);
#pragma unroll
        for (int o = 8; o > 0; o >>= 1)
            dA += __shfl_xor_sync(0xffffffffu, dA, o);
        float exA = half ? 0.f : __expf(dA);
        acc_f16(acc, exA, vA);
        s += exA;
    }

    acc.x += __shfl_xor_sync(0xffffffffu, acc.x, 16);
    acc.y += __shfl_xor_sync(0xffffffffu, acc.y, 16);
    acc.z += __shfl_xor_sync(0xffffffffu, acc.z, 16);
    acc.w += __shfl_xor_sync(0xffffffffu, acc.w, 16);
    s     += __shfl_xor_sync(0xffffffffu, s, 16);

    float r = 1.0f / (s + 1e-16f);
    float4 sk = ((const float4*)(g_skip + (size_t)dst * D))[hl];
    float4 o;
    o.x = fmaf(acc.x, r, sk.x);
    o.y = fmaf(acc.y, r, sk.y);
    o.z = fmaf(acc.z, r, sk.z);
    o.w = fmaf(acc.w, r, sk.w);
    if (lane < 16)
        ((float4*)(out + (size_t)dst * D))[hl] = o;
}

// ---------------------------------------------------------------------------
extern "C" void kernel_launch(void* const* d_in, const int* in_sizes, int n_in,
                              void* d_out, int out_size) {
    const float* x  = (const float*)d_in[0];
    const int*   ei = (const int*)d_in[1];   // int64 in ref -> delivered int32
    // d_in[2] = edge_type (unused by reference)
    const float* Wq = (const float*)d_in[3];
    const float* bq = (const float*)d_in[4];
    const float* Wk = (const float*)d_in[5];
    const float* bk = (const float*)d_in[6];
    const float* Wv = (const float*)d_in[7];
    const float* bv = (const float*)d_in[8];
    const float* Ws = (const float*)d_in[9];
    const float* bs = (const float*)d_in[10];
    float* out = (float*)d_out;

    int n = in_sizes[0] / D;   // 100000
    int E = in_sizes[2];       // 1200000
    if (n > NN) n = NN;
    if (E > EE) E = EE;

    float *gq, *gsk;
    __half *gkh, *gvh;
    cudaGetSymbolAddress((void**)&gq,  g_q);
    cudaGetSymbolAddress((void**)&gkh, g_kh);
    cudaGetSymbolAddress((void**)&gvh, g_vh);
    cudaGetSymbolAddress((void**)&gsk, g_skip);

    int nblk = (n + SCH - 1) / SCH;

    static cudaStream_t s_side = nullptr;
    static cudaEvent_t  ev_fork = nullptr, ev_join = nullptr;
    if (s_side == nullptr) {
        cudaStreamCreateWithFlags(&s_side, cudaStreamNonBlocking);
        cudaEventCreateWithFlags(&ev_fork, cudaEventDisableTiming);
        cudaEventCreateWithFlags(&ev_join, cudaEventDisableTiming);
    }

    // ---- item 1: GEMM on side stream, concurrent with CSR build ----
    cudaEventRecord(ev_fork, 0);
    cudaStreamWaitEvent(s_side, ev_fork, 0);
    {
        dim3 grid((n + GR - 1) / GR, 4);
        gemm_one<<<grid, 128, 0, s_side>>>(x, Wq, bq, Wk, bk, Wv, bv, Ws, bs,
                                           gq, gkh, gvh, gsk, n);
    }
    cudaEventRecord(ev_join, s_side);

    // ---- items 2-4: CSR build on default stream (counts pre-zeroed) ----
    hist_kernel<<<(E / 4 + 255) / 256, 256>>>(ei, E);
    scan_fused<<<nblk, 256>>>(n, nblk);
    scatter_kernel<<<(E / 4 + 255) / 256, 256>>>(ei, E);

    // ---- item 5: gather (after join) ----
    cudaStreamWaitEvent(0, ev_join, 0);
    {
        int warps_per_block = 8;
        int blocks = (n + warps_per_block - 1) / warps_per_block;
        gather_kernel<<<blocks, 256>>>(out, n);
    }

    // ---- item 6: restore zeroed scratch for next replay ----
    tail_zero<<<(n + 255) / 256, 256>>>(n);
}